// round 10
// baseline (speedup 1.0000x reference)
#include <cuda_runtime.h>
#include <cstdint>

#define NG   4
#define NB   4
#define LQ   512
#define NC   768
#define NH   12
#define DH   64
#define MPG  (NB*LQ)           // 2048 rows per group

// Scratch: Q/K/V in head-major layout [((g*NB+b)*NH+h)*LQ + l]*DH + dh
__device__ float g_q[NG*NB*NH*LQ*DH];
__device__ float g_k[NG*NB*NH*LQ*DH];
__device__ float g_v[NG*NB*NH*LQ*DH];
// Transposed weights: [which*4+g][768][768] (row n = W[:,n])
__device__ float g_wt[12*NC*NC];

__device__ __forceinline__ uint32_t f2tf(float f) {
    uint32_t u;
    asm("cvt.rna.tf32.f32 %0, %1;" : "=r"(u) : "f"(f));
    return u;
}
__device__ __forceinline__ float tf(float f) { return __uint_as_float(f2tf(f)); }

__device__ __forceinline__ void mma_tf32(float* d, const uint32_t* a, const uint32_t* b) {
    asm volatile(
        "mma.sync.aligned.m16n8k8.row.col.f32.tf32.tf32.f32 "
        "{%0,%1,%2,%3}, {%4,%5,%6,%7}, {%8,%9}, {%0,%1,%2,%3};"
        : "+f"(d[0]), "+f"(d[1]), "+f"(d[2]), "+f"(d[3])
        : "r"(a[0]), "r"(a[1]), "r"(a[2]), "r"(a[3]), "r"(b[0]), "r"(b[1]));
}

// FMA-pipe exp (avoids MUFU throughput ceiling). rel err ~2e-6.
__device__ __forceinline__ float fast_exp(float x) {
    float t = x * 1.4426950408889634f;
    t = fmaxf(t, -120.0f);
    const int  ei = __float2int_rn(t);
    const float f = t - (float)ei;
    float p =        1.3333558146e-3f;
    p = fmaf(p, f,   9.6181291076e-3f);
    p = fmaf(p, f,   5.5504108664e-2f);
    p = fmaf(p, f,   2.4022650695e-1f);
    p = fmaf(p, f,   6.9314718056e-1f);
    p = fmaf(p, f,   1.0f);
    return p * __int_as_float((ei + 127) << 23);
}

// ---------------------------------------------------------------------------
// Weight transpose: g_wt[w*4+g][n][k] = W_w,g[k][n].  grid (24,24,12), blk (32,8)
// ---------------------------------------------------------------------------
__global__ __launch_bounds__(256) void wt_transpose_kernel(
    const float* __restrict__ qw, const float* __restrict__ kw,
    const float* __restrict__ vw, float* __restrict__ wt)
{
    __shared__ float tile[32][33];
    const int which = blockIdx.z >> 2, g = blockIdx.z & 3;
    const float* W = (which == 0 ? qw : which == 1 ? kw : vw) + (size_t)g * NC * NC;
    float* WT = wt + (size_t)(which * 4 + g) * NC * NC;
    const int tx = threadIdx.x, ty = threadIdx.y;
    const int x = blockIdx.x * 32 + tx;
    const int y = blockIdx.y * 32 + ty;
    #pragma unroll
    for (int j = 0; j < 32; j += 8)
        tile[ty + j][tx] = W[(size_t)(y + j) * NC + x];
    __syncthreads();
    const int x2 = blockIdx.y * 32 + tx;
    const int y2 = blockIdx.x * 32 + ty;
    #pragma unroll
    for (int j = 0; j < 32; j += 8)
        WT[(size_t)(y2 + j) * NC + x2] = tile[tx][ty + j];
}

// ---------------------------------------------------------------------------
// tf32 mma.sync QKV projection (unchanged from R8).
// ---------------------------------------------------------------------------
#define APAD 36
#define BUFF (128*APAD)

__global__ __launch_bounds__(256) void qkv_mma_kernel(
    const float* __restrict__ hs, const float* __restrict__ wt,
    const float* __restrict__ qb, const float* __restrict__ kb, const float* __restrict__ vb,
    float* __restrict__ qp, float* __restrict__ kp, float* __restrict__ vp)
{
    extern __shared__ float sm[];
    float* As = sm;               // [2][128][36]
    float* Bs = sm + 2 * BUFF;    // [2][128][36]

    const int which = blockIdx.z >> 2, g = blockIdx.z & 3;
    const int m0 = blockIdx.y * 128, n0 = blockIdx.x * 128;
    const int tid = threadIdx.x, lane = tid & 31, wid = tid >> 5;
    const int wm = wid & 1, wn = wid >> 1;
    const int gq = lane >> 2, tg = lane & 3;

    const float* Ag = hs + (size_t)g * MPG * NC + (size_t)m0 * NC;
    const float* Bg = wt + (size_t)(which * 4 + g) * NC * NC + (size_t)n0 * NC;
    const float* bg = (which == 0 ? qb : which == 1 ? kb : vb) + (size_t)g * NC;
    float*       op = (which == 0 ? qp : which == 1 ? kp : vp);

    float acc[4][4][4];
    #pragma unroll
    for (int i = 0; i < 4; i++)
        #pragma unroll
        for (int j = 0; j < 4; j++)
            #pragma unroll
            for (int q = 0; q < 4; q++) acc[i][j][q] = 0.f;

    const int lr = tid >> 3;
    const int lc = (tid & 7) * 4;

    float4 pa[4], pb[4];
    #pragma unroll
    for (int i = 0; i < 4; i++) {
        pa[i] = *(const float4*)(Ag + (size_t)(i * 32 + lr) * NC + lc);
        pb[i] = *(const float4*)(Bg + (size_t)(i * 32 + lr) * NC + lc);
    }
    #pragma unroll
    for (int i = 0; i < 4; i++) {
        float* as = As + (i * 32 + lr) * APAD + lc;
        float* bs = Bs + (i * 32 + lr) * APAD + lc;
        as[0] = tf(pa[i].x); as[1] = tf(pa[i].y); as[2] = tf(pa[i].z); as[3] = tf(pa[i].w);
        bs[0] = tf(pb[i].x); bs[1] = tf(pb[i].y); bs[2] = tf(pb[i].z); bs[3] = tf(pb[i].w);
    }
    #pragma unroll
    for (int i = 0; i < 4; i++) {
        pa[i] = *(const float4*)(Ag + (size_t)(i * 32 + lr) * NC + 32 + lc);
        pb[i] = *(const float4*)(Bg + (size_t)(i * 32 + lr) * NC + 32 + lc);
    }
    __syncthreads();

    const int NCH = NC / 32;      // 24
    for (int c = 0; c < NCH; c++) {
        const int buf = c & 1;
        if (c + 1 < NCH) {
            const int nb = buf ^ 1;
            #pragma unroll
            for (int i = 0; i < 4; i++) {
                float* as = As + nb * BUFF + (i * 32 + lr) * APAD + lc;
                float* bs = Bs + nb * BUFF + (i * 32 + lr) * APAD + lc;
                as[0] = tf(pa[i].x); as[1] = tf(pa[i].y); as[2] = tf(pa[i].z); as[3] = tf(pa[i].w);
                bs[0] = tf(pb[i].x); bs[1] = tf(pb[i].y); bs[2] = tf(pb[i].z); bs[3] = tf(pb[i].w);
            }
        }
        if (c + 2 < NCH) {
            const int kc = (c + 2) * 32;
            #pragma unroll
            for (int i = 0; i < 4; i++) {
                pa[i] = *(const float4*)(Ag + (size_t)(i * 32 + lr) * NC + kc + lc);
                pb[i] = *(const float4*)(Bg + (size_t)(i * 32 + lr) * NC + kc + lc);
            }
        }
        {
            const float* Ab = As + buf * BUFF + (wm * 64) * APAD;
            const float* Bb = Bs + buf * BUFF + (wn * 32) * APAD;
            #pragma unroll
            for (int ks = 0; ks < 4; ks++) {
                const int kk = ks * 8;
                uint32_t af[4][4], bf[4][2];
                #pragma unroll
                for (int mt = 0; mt < 4; mt++) {
                    const float* ap = Ab + (mt * 16 + gq) * APAD + kk + tg;
                    af[mt][0] = __float_as_uint(ap[0]);
                    af[mt][1] = __float_as_uint(ap[8 * APAD]);
                    af[mt][2] = __float_as_uint(ap[4]);
                    af[mt][3] = __float_as_uint(ap[8 * APAD + 4]);
                }
                #pragma unroll
                for (int nt = 0; nt < 4; nt++) {
                    const float* bp = Bb + (nt * 8 + gq) * APAD + kk + tg;
                    bf[nt][0] = __float_as_uint(bp[0]);
                    bf[nt][1] = __float_as_uint(bp[4]);
                }
                #pragma unroll
                for (int mt = 0; mt < 4; mt++)
                    #pragma unroll
                    for (int nt = 0; nt < 4; nt++)
                        mma_tf32(acc[mt][nt], af[mt], bf[nt]);
            }
        }
        __syncthreads();
    }

    #pragma unroll
    for (int mt = 0; mt < 4; mt++) {
        const int row0 = m0 + wm * 64 + mt * 16 + gq;
        #pragma unroll
        for (int half = 0; half < 2; half++) {
            const int trow = row0 + half * 8;
            const int b = trow >> 9, l = trow & 511;
            #pragma unroll
            for (int nt = 0; nt < 4; nt++) {
                const int col = n0 + wn * 32 + nt * 8 + 2 * tg;
                const int h = col >> 6, dh = col & 63;
                const float2 bv = *(const float2*)(bg + col);
                float2 o;
                o.x = acc[mt][nt][half * 2 + 0] + bv.x;
                o.y = acc[mt][nt][half * 2 + 1] + bv.y;
                *(float2*)(op + ((((size_t)g * NB + b) * NH + h) * LQ + l) * DH + dh) = o;
            }
        }
    }
}

// ---------------------------------------------------------------------------
// Resident-KV flash attention, tf32 mma.sync, 512 threads (16 warps).
// One CTA per (gbh, 32 queries). Warp w owns keys [w*32, w*32+32).
// Scores/exp stay in registers; P -> A-fragment via intra-quad shuffles.
// smem: Qs[32][68] | mask[512] | wmax[16][32] | wsum[16][32] | inv[32] |
//       KV[512][72] (K phase stride 68; Cred[16][32][68] aliases KV)
// ---------------------------------------------------------------------------
#define QT   32
#define QP   68
#define KSTR 68
#define VSTR 72
#define CRS  68
#define ATHR 512
#define SM_MSK  (QT*QP)             // 2176
#define SM_WMAX (SM_MSK + 512)      // 2688
#define SM_WSUM (SM_WMAX + 512)     // 3200
#define SM_INV  (SM_WSUM + 512)     // 3712
#define SM_KV   (SM_INV + 32)       // 3744
#define AFL_TOT (SM_KV + 512*VSTR)  // 40608 floats = 162432 B

// Build A-fragment (rows gq/gq+8, k cols tg/tg+4) from a C-fragment held in
// quad lanes: element (r, c) lives in lane (r-quad, c>>1) at index c&1.
__device__ __forceinline__ void p_relayout(const float c[4], uint32_t a[4],
                                           int lane, int tg) {
    const int src1 = (lane & ~3) | (tg >> 1);
    const int src2 = src1 + 2;
    const bool odd = (tg & 1);
    float x0 = __shfl_sync(0xFFFFFFFFu, c[0], src1);
    float x1 = __shfl_sync(0xFFFFFFFFu, c[1], src1);
    a[0] = __float_as_uint(odd ? x1 : x0);
    float y0 = __shfl_sync(0xFFFFFFFFu, c[2], src1);
    float y1 = __shfl_sync(0xFFFFFFFFu, c[3], src1);
    a[1] = __float_as_uint(odd ? y1 : y0);
    x0 = __shfl_sync(0xFFFFFFFFu, c[0], src2);
    x1 = __shfl_sync(0xFFFFFFFFu, c[1], src2);
    a[2] = __float_as_uint(odd ? x1 : x0);
    y0 = __shfl_sync(0xFFFFFFFFu, c[2], src2);
    y1 = __shfl_sync(0xFFFFFFFFu, c[3], src2);
    a[3] = __float_as_uint(odd ? y1 : y0);
}

__global__ __launch_bounds__(ATHR, 1) void attn_flash_kernel(
    const float* __restrict__ qg, const float* __restrict__ kg,
    const float* __restrict__ vg, const float* __restrict__ mask,
    float* __restrict__ out)
{
    extern __shared__ float sm[];
    float* Qs   = sm;
    float* Msk  = sm + SM_MSK;
    float* Wmax = sm + SM_WMAX;
    float* Wsum = sm + SM_WSUM;
    float* Invs = sm + SM_INV;
    float* KV   = sm + SM_KV;
    float* Cred = KV;                 // alias (used after V is dead)

    const int gbh = blockIdx.y;
    const int l0  = blockIdx.x * QT;
    const int h   = gbh % NH;
    const int gb  = gbh / NH;
    const int tid  = threadIdx.x;
    const int lane = tid & 31;
    const int wid  = tid >> 5;          // 0..15
    const int gq = lane >> 2, tg = lane & 3;

    const float* Q  = qg + (size_t)gbh * LQ * DH;
    const float* K  = kg + (size_t)gbh * LQ * DH;
    const float* V  = vg + (size_t)gbh * LQ * DH;
    const float* mk = mask + (size_t)gb * LQ;

    // ---- loads: Q tile (1 float4/thread), mask, full K (stride 68, uint4 STS) ----
    {
        const int row = tid >> 4, c4 = (tid & 15) * 4;
        const float4 v = *(const float4*)(Q + (size_t)(l0 + row) * DH + c4);
        *(uint4*)(Qs + row * QP + c4) =
            make_uint4(f2tf(v.x), f2tf(v.y), f2tf(v.z), f2tf(v.w));
    }
    Msk[tid] = mk[tid];
    #pragma unroll
    for (int i = 0; i < 8; i++) {
        const int idx = i * ATHR + tid;
        const int r = idx >> 3, c8 = (idx & 7) * 8;
        const float4 a = *(const float4*)(K + (size_t)r * DH + c8);
        const float4 b = *(const float4*)(K + (size_t)r * DH + c8 + 4);
        *(uint4*)(KV + r * KSTR + c8)     = make_uint4(f2tf(a.x), f2tf(a.y), f2tf(a.z), f2tf(a.w));
        *(uint4*)(KV + r * KSTR + c8 + 4) = make_uint4(f2tf(b.x), f2tf(b.y), f2tf(b.z), f2tf(b.w));
    }
    __syncthreads();   // S1

    // ---- Q fragments to registers ----
    uint32_t qf[2][8][4];
    #pragma unroll
    for (int ks = 0; ks < 8; ks++) {
        const int kk = ks * 8;
        #pragma unroll
        for (int mt = 0; mt < 2; mt++) {
            const float* ap = Qs + (mt * 16 + gq) * QP + kk + tg;
            qf[mt][ks][0] = __float_as_uint(ap[0]);
            qf[mt][ks][1] = __float_as_uint(ap[8 * QP]);
            qf[mt][ks][2] = __float_as_uint(ap[4]);
            qf[mt][ks][3] = __float_as_uint(ap[8 * QP + 4]);
        }
    }

    // ---- phase 1: S (32 x 32 per warp) in registers ----
    float sacc[2][4][4];
    #pragma unroll
    for (int mt = 0; mt < 2; mt++)
        #pragma unroll
        for (int nt = 0; nt < 4; nt++)
            #pragma unroll
            for (int q = 0; q < 4; q++) sacc[mt][nt][q] = 0.f;

    const float* Kb = KV + wid * 32 * KSTR;
    #pragma unroll
    for (int ks = 0; ks < 8; ks++) {
        const int kk = ks * 8;
        #pragma unroll
        for (int nt = 0; nt < 4; nt++) {
            uint32_t bf[2];
            const float* bp = Kb + (nt * 8 + gq) * KSTR + kk + tg;
            bf[0] = __float_as_uint(bp[0]);
            bf[1] = __float_as_uint(bp[4]);
            mma_tf32(sacc[0][nt], qf[0][ks], bf);
            mma_tf32(sacc[1][nt], qf[1][ks], bf);
        }
    }

    // ---- scale + mask + local row max ----
    const float scale = 0.125f;
    float lm[2][2];
    lm[0][0] = lm[0][1] = lm[1][0] = lm[1][1] = -1e30f;
    #pragma unroll
    for (int mt = 0; mt < 2; mt++)
        #pragma unroll
        for (int nt = 0; nt < 4; nt++) {
            const int col = wid * 32 + nt * 8 + 2 * tg;
            const float m0v = Msk[col], m1v = Msk[col + 1];
            float* s = sacc[mt][nt];
            s[0] = fmaf(s[0], scale, m0v);
            s[1] = fmaf(s[1], scale, m1v);
            s[2] = fmaf(s[2], scale, m0v);
            s[3] = fmaf(s[3], scale, m1v);
            lm[mt][0] = fmaxf(lm[mt][0], fmaxf(s[0], s[1]));
            lm[mt][1] = fmaxf(lm[mt][1], fmaxf(s[2], s[3]));
        }
    #pragma unroll
    for (int mt = 0; mt < 2; mt++)
        #pragma unroll
        for (int hf = 0; hf < 2; hf++) {
            float m = lm[mt][hf];
            m = fmaxf(m, __shfl_xor_sync(0xFFFFFFFFu, m, 1));
            m = fmaxf(m, __shfl_xor_sync(0xFFFFFFFFu, m, 2));
            lm[mt][hf] = m;
        }
    if (tg == 0) {
        Wmax[wid * 32 + gq]      = lm[0][0];
        Wmax[wid * 32 + gq + 8]  = lm[0][1];
        Wmax[wid * 32 + gq + 16] = lm[1][0];
        Wmax[wid * 32 + gq + 24] = lm[1][1];
    }
    __syncthreads();   // S2 (all K reads done; Wmax published)

    // ---- global max, exp in regs, local sum ----
    float gmax[2][2];
    #pragma unroll
    for (int mt = 0; mt < 2; mt++)
        #pragma unroll
        for (int hf = 0; hf < 2; hf++) {
            const int r = mt * 16 + gq + hf * 8;
            float m = -1e30f;
            #pragma unroll
            for (int w = 0; w < 16; w++) m = fmaxf(m, Wmax[w * 32 + r]);
            gmax[mt][hf] = m;
        }
    float ls[2][2] = {{0.f, 0.f}, {0.f, 0.f}};
    #pragma unroll
    for (int mt = 0; mt < 2; mt++)
        #pragma unroll
        for (int nt = 0; nt < 4; nt++) {
            float* s = sacc[mt][nt];
            float e0 = fast_exp(s[0] - gmax[mt][0]);
            float e1 = fast_exp(s[1] - gmax[mt][0]);
            float e2 = fast_exp(s[2] - gmax[mt][1]);
            float e3 = fast_exp(s[3] - gmax[mt][1]);
            ls[mt][0] += e0 + e1;
            ls[mt][1] += e2 + e3;
            s[0] = tf(e0); s[1] = tf(e1); s[2] = tf(e2); s[3] = tf(e3);
        }
    #pragma unroll
    for (int mt = 0; mt < 2; mt++)
        #pragma unroll
        for (int hf = 0; hf < 2; hf++) {
            float v = ls[mt][hf];
            v += __shfl_xor_sync(0xFFFFFFFFu, v, 1);
            v += __shfl_xor_sync(0xFFFFFFFFu, v, 2);
            ls[mt][hf] = v;
        }
    if (tg == 0) {
        Wsum[wid * 32 + gq]      = ls[0][0];
        Wsum[wid * 32 + gq + 8]  = ls[0][1];
        Wsum[wid * 32 + gq + 16] = ls[1][0];
        Wsum[wid * 32 + gq + 24] = ls[1][1];
    }

    // ---- V load (stride 72) overlaps softmax tail; K region is dead ----
    #pragma unroll
    for (int i = 0; i < 8; i++) {
        const int idx = i * ATHR + tid;
        const int r = idx >> 3, c8 = (idx & 7) * 8;
        const float4 a = *(const float4*)(V + (size_t)r * DH + c8);
        const float4 b = *(const float4*)(V + (size_t)r * DH + c8 + 4);
        *(uint4*)(KV + r * VSTR + c8)     = make_uint4(f2tf(a.x), f2tf(a.y), f2tf(a.z), f2tf(a.w));
        *(uint4*)(KV + r * VSTR + c8 + 4) = make_uint4(f2tf(b.x), f2tf(b.y), f2tf(b.z), f2tf(b.w));
    }
    __syncthreads();   // S3 (covers Wsum + V)

    if (wid == 0 && tg == 0) {
        #pragma unroll
        for (int j = 0; j < 4; j++) {
            const int r = j * 8 + gq;
            float ssum = 0.f;
            #pragma unroll
            for (int w = 0; w < 16; w++) ssum += Wsum[w * 32 + r];
            Invs[r] = 1.0f / ssum;
        }
    }

    // ---- phase 3: ctx_w = P_w @ V_w (per-warp 32-key strip) ----
    float ctx[2][8][4];
    #pragma unroll
    for (int mt = 0; mt < 2; mt++)
        #pragma unroll
        for (int ntd = 0; ntd < 8; ntd++)
            #pragma unroll
            for (int q = 0; q < 4; q++) ctx[mt][ntd][q] = 0.f;

    const float* Vb = KV + wid * 32 * VSTR;
    #pragma unroll
    for (int nt = 0; nt < 4; nt++) {          // k-tiles over this warp's 32 keys
        uint32_t a0[4], a1[4];
        p_relayout(sacc[0][nt], a0, lane, tg);
        p_relayout(sacc[1][nt], a1, lane, tg);
        #pragma unroll
        for (int ntd = 0; ntd < 8; ntd++) {
            uint32_t bf[2];
            bf[0] = __float_as_uint(Vb[(nt * 8 + tg) * VSTR + ntd * 8 + gq]);
            bf[1] = __float_as_uint(Vb[(nt * 8 + tg + 4) * VSTR + ntd * 8 + gq]);
            mma_tf32(ctx[0][ntd], a0, bf);
            mma_tf32(ctx[1][ntd], a1, bf);
        }
    }
    __syncthreads();   // S4: all V reads done; Invs published

    // ---- cross-warp ctx reduce through smem (aliased over KV) ----
    float* Cw = Cred + wid * 32 * CRS;
    #pragma unroll
    for (int mt = 0; mt < 2; mt++)
        #pragma unroll
        for (int ntd = 0; ntd < 8; ntd++) {
            *(float2*)(Cw + (mt * 16 + gq) * CRS + ntd * 8 + 2 * tg) =
                make_float2(ctx[mt][ntd][0], ctx[mt][ntd][1]);
            *(float2*)(Cw + (mt * 16 + gq + 8) * CRS + ntd * 8 + 2 * tg) =
                make_float2(ctx[mt][ntd][2], ctx[mt][ntd][3]);
        }
    __syncthreads();   // S5

    {
        const int row = tid >> 4;            // 0..31
        const int c4  = (tid & 15) * 4;      // 0..60
        float4 s = make_float4(0.f, 0.f, 0.f, 0.f);
        #pragma unroll
        for (int w = 0; w < 16; w++) {
            const float4 t = *(const float4*)(Cred + w * 32 * CRS + row * CRS + c4);
            s.x += t.x; s.y += t.y; s.z += t.z; s.w += t.w;
        }
        const float iv = Invs[row];
        float* orow = out + ((size_t)gb * LQ + l0 + row) * NC + h * DH + c4;
        *(float4*)(orow) = make_float4(s.x * iv, s.y * iv, s.z * iv, s.w * iv);
    }
}

// ---------------------------------------------------------------------------
extern "C" void kernel_launch(void* const* d_in, const int* in_sizes, int n_in,
                              void* d_out, int out_size)
{
    (void)in_sizes; (void)n_in; (void)out_size;
    const float* hs   = (const float*)d_in[0];
    const float* mask = (const float*)d_in[1];
    const float* qw   = (const float*)d_in[2];
    const float* qb   = (const float*)d_in[3];
    const float* kw   = (const float*)d_in[4];
    const float* kb   = (const float*)d_in[5];
    const float* vw   = (const float*)d_in[6];
    const float* vb   = (const float*)d_in[7];
    float* out = (float*)d_out;

    float *qp, *kp, *vp, *wtp;
    cudaGetSymbolAddress((void**)&qp, g_q);
    cudaGetSymbolAddress((void**)&kp, g_k);
    cudaGetSymbolAddress((void**)&vp, g_v);
    cudaGetSymbolAddress((void**)&wtp, g_wt);

    dim3 tgrid(NC / 32, NC / 32, 12);
    wt_transpose_kernel<<<tgrid, dim3(32, 8)>>>(qw, kw, vw, wtp);

    const int gsmem = 4 * BUFF * (int)sizeof(float);   // 73728
    cudaFuncSetAttribute(qkv_mma_kernel,
                         cudaFuncAttributeMaxDynamicSharedMemorySize, gsmem);
    dim3 ggrid(NC / 128, MPG / 128, 12);
    qkv_mma_kernel<<<ggrid, 256, gsmem>>>(hs, wtp, qb, kb, vb, qp, kp, vp);

    const int asmem = AFL_TOT * (int)sizeof(float);    // 162432
    cudaFuncSetAttribute(attn_flash_kernel,
                         cudaFuncAttributeMaxDynamicSharedMemorySize, asmem);
    dim3 agrid(LQ / QT, NG * NB * NH);
    attn_flash_kernel<<<agrid, ATHR, asmem>>>(qp, kp, vp, mask, out);
}

// round 11
// speedup vs baseline: 1.2703x; 1.2703x over previous
#include <cuda_runtime.h>
#include <cuda_fp16.h>
#include <cstdint>

#define NG   4
#define NB   4
#define LQ   512
#define NC   768
#define NH   12
#define DH   64
#define MPG  (NB*LQ)           // 2048 rows per group

// Scratch: Q/K/V in head-major layout [((g*NB+b)*NH+h)*LQ + l]*DH + dh
__device__ float g_q[NG*NB*NH*LQ*DH];
__device__ float g_k[NG*NB*NH*LQ*DH];
__device__ float g_v[NG*NB*NH*LQ*DH];
// Transposed weights: [which*4+g][768][768] (row n = W[:,n])
__device__ float g_wt[12*NC*NC];

__device__ __forceinline__ uint32_t f2tf(float f) {
    uint32_t u;
    asm("cvt.rna.tf32.f32 %0, %1;" : "=r"(u) : "f"(f));
    return u;
}
__device__ __forceinline__ float tf(float f) { return __uint_as_float(f2tf(f)); }

__device__ __forceinline__ void mma_tf32(float* d, const uint32_t* a, const uint32_t* b) {
    asm volatile(
        "mma.sync.aligned.m16n8k8.row.col.f32.tf32.tf32.f32 "
        "{%0,%1,%2,%3}, {%4,%5,%6,%7}, {%8,%9}, {%0,%1,%2,%3};"
        : "+f"(d[0]), "+f"(d[1]), "+f"(d[2]), "+f"(d[3])
        : "r"(a[0]), "r"(a[1]), "r"(a[2]), "r"(a[3]), "r"(b[0]), "r"(b[1]));
}

__device__ __forceinline__ void mma_f16(float* d, const uint32_t* a, const uint32_t* b) {
    asm volatile(
        "mma.sync.aligned.m16n8k16.row.col.f32.f16.f16.f32 "
        "{%0,%1,%2,%3}, {%4,%5,%6,%7}, {%8,%9}, {%0,%1,%2,%3};"
        : "+f"(d[0]), "+f"(d[1]), "+f"(d[2]), "+f"(d[3])
        : "r"(a[0]), "r"(a[1]), "r"(a[2]), "r"(a[3]), "r"(b[0]), "r"(b[1]));
}

__device__ __forceinline__ void ldmx2t(uint32_t& b0, uint32_t& b1, uint32_t saddr) {
    asm volatile("ldmatrix.sync.aligned.m8n8.x2.trans.shared.b16 {%0,%1}, [%2];"
                 : "=r"(b0), "=r"(b1) : "r"(saddr));
}

__device__ __forceinline__ uint32_t pkh(float a, float b) {
    __half2 h = __floats2half2_rn(a, b);
    return *(uint32_t*)&h;
}

// FMA-pipe exp (avoids MUFU throughput ceiling). rel err ~2e-6.
__device__ __forceinline__ float fast_exp(float x) {
    float t = x * 1.4426950408889634f;
    t = fmaxf(t, -120.0f);
    const int  ei = __float2int_rn(t);
    const float f = t - (float)ei;
    float p =        1.3333558146e-3f;
    p = fmaf(p, f,   9.6181291076e-3f);
    p = fmaf(p, f,   5.5504108664e-2f);
    p = fmaf(p, f,   2.4022650695e-1f);
    p = fmaf(p, f,   6.9314718056e-1f);
    p = fmaf(p, f,   1.0f);
    return p * __int_as_float((ei + 127) << 23);
}

// ---------------------------------------------------------------------------
// Weight transpose: g_wt[w*4+g][n][k] = W_w,g[k][n].  grid (24,24,12), blk (32,8)
// ---------------------------------------------------------------------------
__global__ __launch_bounds__(256) void wt_transpose_kernel(
    const float* __restrict__ qw, const float* __restrict__ kw,
    const float* __restrict__ vw, float* __restrict__ wt)
{
    __shared__ float tile[32][33];
    const int which = blockIdx.z >> 2, g = blockIdx.z & 3;
    const float* W = (which == 0 ? qw : which == 1 ? kw : vw) + (size_t)g * NC * NC;
    float* WT = wt + (size_t)(which * 4 + g) * NC * NC;
    const int tx = threadIdx.x, ty = threadIdx.y;
    const int x = blockIdx.x * 32 + tx;
    const int y = blockIdx.y * 32 + ty;
    #pragma unroll
    for (int j = 0; j < 32; j += 8)
        tile[ty + j][tx] = W[(size_t)(y + j) * NC + x];
    __syncthreads();
    const int x2 = blockIdx.y * 32 + tx;
    const int y2 = blockIdx.x * 32 + ty;
    #pragma unroll
    for (int j = 0; j < 32; j += 8)
        WT[(size_t)(y2 + j) * NC + x2] = tile[tx][ty + j];
}

// ---------------------------------------------------------------------------
// tf32 mma.sync QKV projection (unchanged from R8).
// ---------------------------------------------------------------------------
#define APAD 36
#define BUFF (128*APAD)

__global__ __launch_bounds__(256) void qkv_mma_kernel(
    const float* __restrict__ hs, const float* __restrict__ wt,
    const float* __restrict__ qb, const float* __restrict__ kb, const float* __restrict__ vb,
    float* __restrict__ qp, float* __restrict__ kp, float* __restrict__ vp)
{
    extern __shared__ float sm[];
    float* As = sm;               // [2][128][36]
    float* Bs = sm + 2 * BUFF;    // [2][128][36]

    const int which = blockIdx.z >> 2, g = blockIdx.z & 3;
    const int m0 = blockIdx.y * 128, n0 = blockIdx.x * 128;
    const int tid = threadIdx.x, lane = tid & 31, wid = tid >> 5;
    const int wm = wid & 1, wn = wid >> 1;
    const int gq = lane >> 2, tg = lane & 3;

    const float* Ag = hs + (size_t)g * MPG * NC + (size_t)m0 * NC;
    const float* Bg = wt + (size_t)(which * 4 + g) * NC * NC + (size_t)n0 * NC;
    const float* bg = (which == 0 ? qb : which == 1 ? kb : vb) + (size_t)g * NC;
    float*       op = (which == 0 ? qp : which == 1 ? kp : vp);

    float acc[4][4][4];
    #pragma unroll
    for (int i = 0; i < 4; i++)
        #pragma unroll
        for (int j = 0; j < 4; j++)
            #pragma unroll
            for (int q = 0; q < 4; q++) acc[i][j][q] = 0.f;

    const int lr = tid >> 3;
    const int lc = (tid & 7) * 4;

    float4 pa[4], pb[4];
    #pragma unroll
    for (int i = 0; i < 4; i++) {
        pa[i] = *(const float4*)(Ag + (size_t)(i * 32 + lr) * NC + lc);
        pb[i] = *(const float4*)(Bg + (size_t)(i * 32 + lr) * NC + lc);
    }
    #pragma unroll
    for (int i = 0; i < 4; i++) {
        float* as = As + (i * 32 + lr) * APAD + lc;
        float* bs = Bs + (i * 32 + lr) * APAD + lc;
        as[0] = tf(pa[i].x); as[1] = tf(pa[i].y); as[2] = tf(pa[i].z); as[3] = tf(pa[i].w);
        bs[0] = tf(pb[i].x); bs[1] = tf(pb[i].y); bs[2] = tf(pb[i].z); bs[3] = tf(pb[i].w);
    }
    #pragma unroll
    for (int i = 0; i < 4; i++) {
        pa[i] = *(const float4*)(Ag + (size_t)(i * 32 + lr) * NC + 32 + lc);
        pb[i] = *(const float4*)(Bg + (size_t)(i * 32 + lr) * NC + 32 + lc);
    }
    __syncthreads();

    const int NCH = NC / 32;      // 24
    for (int c = 0; c < NCH; c++) {
        const int buf = c & 1;
        if (c + 1 < NCH) {
            const int nb = buf ^ 1;
            #pragma unroll
            for (int i = 0; i < 4; i++) {
                float* as = As + nb * BUFF + (i * 32 + lr) * APAD + lc;
                float* bs = Bs + nb * BUFF + (i * 32 + lr) * APAD + lc;
                as[0] = tf(pa[i].x); as[1] = tf(pa[i].y); as[2] = tf(pa[i].z); as[3] = tf(pa[i].w);
                bs[0] = tf(pb[i].x); bs[1] = tf(pb[i].y); bs[2] = tf(pb[i].z); bs[3] = tf(pb[i].w);
            }
        }
        if (c + 2 < NCH) {
            const int kc = (c + 2) * 32;
            #pragma unroll
            for (int i = 0; i < 4; i++) {
                pa[i] = *(const float4*)(Ag + (size_t)(i * 32 + lr) * NC + kc + lc);
                pb[i] = *(const float4*)(Bg + (size_t)(i * 32 + lr) * NC + kc + lc);
            }
        }
        {
            const float* Ab = As + buf * BUFF + (wm * 64) * APAD;
            const float* Bb = Bs + buf * BUFF + (wn * 32) * APAD;
            #pragma unroll
            for (int ks = 0; ks < 4; ks++) {
                const int kk = ks * 8;
                uint32_t af[4][4], bf[4][2];
                #pragma unroll
                for (int mt = 0; mt < 4; mt++) {
                    const float* ap = Ab + (mt * 16 + gq) * APAD + kk + tg;
                    af[mt][0] = __float_as_uint(ap[0]);
                    af[mt][1] = __float_as_uint(ap[8 * APAD]);
                    af[mt][2] = __float_as_uint(ap[4]);
                    af[mt][3] = __float_as_uint(ap[8 * APAD + 4]);
                }
                #pragma unroll
                for (int nt = 0; nt < 4; nt++) {
                    const float* bp = Bb + (nt * 8 + gq) * APAD + kk + tg;
                    bf[nt][0] = __float_as_uint(bp[0]);
                    bf[nt][1] = __float_as_uint(bp[4]);
                }
                #pragma unroll
                for (int mt = 0; mt < 4; mt++)
                    #pragma unroll
                    for (int nt = 0; nt < 4; nt++)
                        mma_tf32(acc[mt][nt], af[mt], bf[nt]);
            }
        }
        __syncthreads();
    }

    #pragma unroll
    for (int mt = 0; mt < 4; mt++) {
        const int row0 = m0 + wm * 64 + mt * 16 + gq;
        #pragma unroll
        for (int half = 0; half < 2; half++) {
            const int trow = row0 + half * 8;
            const int b = trow >> 9, l = trow & 511;
            #pragma unroll
            for (int nt = 0; nt < 4; nt++) {
                const int col = n0 + wn * 32 + nt * 8 + 2 * tg;
                const int h = col >> 6, dh = col & 63;
                const float2 bv = *(const float2*)(bg + col);
                float2 o;
                o.x = acc[mt][nt][half * 2 + 0] + bv.x;
                o.y = acc[mt][nt][half * 2 + 1] + bv.y;
                *(float2*)(op + ((((size_t)g * NB + b) * NH + h) * LQ + l) * DH + dh) = o;
            }
        }
    }
}

// ---------------------------------------------------------------------------
// Resident-KV flash attention, fp16 mma.sync (m16n8k16), 256 threads (8 warps).
// One CTA per (gbh, 32 queries); warp w owns keys [w*64, w*64+64).
// Scores/exp in registers; exp'd P packs DIRECTLY into fp16 A-fragments (no
// shuffles). V B-fragments via ldmatrix.x2.trans. K/V half2 in smem -> 82.5KB
// -> 2 CTAs/SM.
// smem (u32 units): Qs[32][36] | mask[512]f | wmax[8][32]f | wsum[8][32]f |
//                   inv[32]f | KV[512][36] (Cred[8][32][68]f aliases KV)
// ---------------------------------------------------------------------------
#define QT   32
#define QSP  36
#define KSP  36
#define CRS  68
#define O_QS   0
#define O_MSK  1152
#define O_WMAX 1664
#define O_WSUM 1920
#define O_INV  2176
#define O_KV   2208
#define ASM_U32 (O_KV + 512*KSP)    // 20640 u32 = 82560 B

__global__ __launch_bounds__(256, 2) void attn_flash_kernel(
    const float* __restrict__ qg, const float* __restrict__ kg,
    const float* __restrict__ vg, const float* __restrict__ mask,
    float* __restrict__ out)
{
    extern __shared__ uint32_t smu[];
    uint32_t* Qs   = smu + O_QS;
    float*    Msk  = (float*)(smu + O_MSK);
    float*    Wmax = (float*)(smu + O_WMAX);
    float*    Wsum = (float*)(smu + O_WSUM);
    float*    Invs = (float*)(smu + O_INV);
    uint32_t* KV   = smu + O_KV;
    float*    Cred = (float*)(smu + O_KV);   // alias (used after V is dead)

    const int gbh = blockIdx.y;
    const int l0  = blockIdx.x * QT;
    const int h   = gbh % NH;
    const int gb  = gbh / NH;
    const int tid  = threadIdx.x;
    const int lane = tid & 31;
    const int wid  = tid >> 5;          // 0..7
    const int gq = lane >> 2, tg = lane & 3;

    const float* Q  = qg + (size_t)gbh * LQ * DH;
    const float* K  = kg + (size_t)gbh * LQ * DH;
    const float* V  = vg + (size_t)gbh * LQ * DH;
    const float* mk = mask + (size_t)gb * LQ;

    // ---- loads: Q tile (half2), mask, full K (half2, stride 36 u32) ----
    #pragma unroll
    for (int i = 0; i < 2; i++) {
        const int idx = i * 256 + tid;
        const int row = idx >> 4, c4 = (idx & 15) * 4;
        const float4 v = *(const float4*)(Q + (size_t)(l0 + row) * DH + c4);
        *(uint2*)(Qs + row * QSP + c4 / 2) = make_uint2(pkh(v.x, v.y), pkh(v.z, v.w));
    }
    Msk[tid] = mk[tid];
    Msk[tid + 256] = mk[tid + 256];
    #pragma unroll
    for (int i = 0; i < 16; i++) {
        const int idx = i * 256 + tid;
        const int r = idx >> 3, c8 = (idx & 7) * 8;
        const float4 a = *(const float4*)(K + (size_t)r * DH + c8);
        const float4 b = *(const float4*)(K + (size_t)r * DH + c8 + 4);
        *(uint4*)(KV + r * KSP + c8 / 2) =
            make_uint4(pkh(a.x, a.y), pkh(a.z, a.w), pkh(b.x, b.y), pkh(b.z, b.w));
    }
    __syncthreads();   // S1

    // ---- Q fragments (m16n8k16) to registers ----
    uint32_t qf[2][4][4];
    #pragma unroll
    for (int ks = 0; ks < 4; ks++) {
        #pragma unroll
        for (int mt = 0; mt < 2; mt++) {
            const uint32_t* ap = Qs + (mt * 16 + gq) * QSP + ks * 8 + tg;
            qf[mt][ks][0] = ap[0];
            qf[mt][ks][1] = ap[8 * QSP];
            qf[mt][ks][2] = ap[4];
            qf[mt][ks][3] = ap[8 * QSP + 4];
        }
    }

    // ---- phase 1: S (32 x 64 per warp) in registers ----
    float sacc[2][8][4];
    #pragma unroll
    for (int mt = 0; mt < 2; mt++)
        #pragma unroll
        for (int nt = 0; nt < 8; nt++)
            #pragma unroll
            for (int q = 0; q < 4; q++) sacc[mt][nt][q] = 0.f;

    const uint32_t* Kb = KV + wid * 64 * KSP;
    #pragma unroll
    for (int ks = 0; ks < 4; ks++) {
        #pragma unroll
        for (int nt = 0; nt < 8; nt++) {
            uint32_t bf[2];
            const uint32_t* bp = Kb + (nt * 8 + gq) * KSP + ks * 8 + tg;
            bf[0] = bp[0];
            bf[1] = bp[4];
            mma_f16(sacc[0][nt], qf[0][ks], bf);
            mma_f16(sacc[1][nt], qf[1][ks], bf);
        }
    }

    // ---- scale + mask + local row max ----
    const float scale = 0.125f;
    float lm[2][2];
    lm[0][0] = lm[0][1] = lm[1][0] = lm[1][1] = -1e30f;
    #pragma unroll
    for (int mt = 0; mt < 2; mt++)
        #pragma unroll
        for (int nt = 0; nt < 8; nt++) {
            const int col = wid * 64 + nt * 8 + 2 * tg;
            const float m0v = Msk[col], m1v = Msk[col + 1];
            float* s = sacc[mt][nt];
            s[0] = fmaf(s[0], scale, m0v);
            s[1] = fmaf(s[1], scale, m1v);
            s[2] = fmaf(s[2], scale, m0v);
            s[3] = fmaf(s[3], scale, m1v);
            lm[mt][0] = fmaxf(lm[mt][0], fmaxf(s[0], s[1]));
            lm[mt][1] = fmaxf(lm[mt][1], fmaxf(s[2], s[3]));
        }
    #pragma unroll
    for (int mt = 0; mt < 2; mt++)
        #pragma unroll
        for (int hf = 0; hf < 2; hf++) {
            float m = lm[mt][hf];
            m = fmaxf(m, __shfl_xor_sync(0xFFFFFFFFu, m, 1));
            m = fmaxf(m, __shfl_xor_sync(0xFFFFFFFFu, m, 2));
            lm[mt][hf] = m;
        }
    if (tg == 0) {
        Wmax[wid * 32 + gq]      = lm[0][0];
        Wmax[wid * 32 + gq + 8]  = lm[0][1];
        Wmax[wid * 32 + gq + 16] = lm[1][0];
        Wmax[wid * 32 + gq + 24] = lm[1][1];
    }
    __syncthreads();   // S2 (all K reads done; Wmax published)

    // ---- global max, exp in regs -> packed half2 A-frags, local sum ----
    float gmax[2][2];
    #pragma unroll
    for (int mt = 0; mt < 2; mt++)
        #pragma unroll
        for (int hf = 0; hf < 2; hf++) {
            const int r = mt * 16 + gq + hf * 8;
            float m = -1e30f;
            #pragma unroll
            for (int w = 0; w < 8; w++) m = fmaxf(m, Wmax[w * 32 + r]);
            gmax[mt][hf] = m;
        }
    float ls[2][2] = {{0.f, 0.f}, {0.f, 0.f}};
    uint32_t ph[2][8][2];
    #pragma unroll
    for (int mt = 0; mt < 2; mt++)
        #pragma unroll
        for (int nt = 0; nt < 8; nt++) {
            const float* s = sacc[mt][nt];
            const float e0 = fast_exp(s[0] - gmax[mt][0]);
            const float e1 = fast_exp(s[1] - gmax[mt][0]);
            const float e2 = fast_exp(s[2] - gmax[mt][1]);
            const float e3 = fast_exp(s[3] - gmax[mt][1]);
            ls[mt][0] += e0 + e1;
            ls[mt][1] += e2 + e3;
            ph[mt][nt][0] = pkh(e0, e1);
            ph[mt][nt][1] = pkh(e2, e3);
        }
    #pragma unroll
    for (int mt = 0; mt < 2; mt++)
        #pragma unroll
        for (int hf = 0; hf < 2; hf++) {
            float v = ls[mt][hf];
            v += __shfl_xor_sync(0xFFFFFFFFu, v, 1);
            v += __shfl_xor_sync(0xFFFFFFFFu, v, 2);
            ls[mt][hf] = v;
        }
    if (tg == 0) {
        Wsum[wid * 32 + gq]      = ls[0][0];
        Wsum[wid * 32 + gq + 8]  = ls[0][1];
        Wsum[wid * 32 + gq + 16] = ls[1][0];
        Wsum[wid * 32 + gq + 24] = ls[1][1];
    }

    // ---- V load (half2, same region; K is dead) ----
    #pragma unroll
    for (int i = 0; i < 16; i++) {
        const int idx = i * 256 + tid;
        const int r = idx >> 3, c8 = (idx & 7) * 8;
        const float4 a = *(const float4*)(V + (size_t)r * DH + c8);
        const float4 b = *(const float4*)(V + (size_t)r * DH + c8 + 4);
        *(uint4*)(KV + r * KSP + c8 / 2) =
            make_uint4(pkh(a.x, a.y), pkh(a.z, a.w), pkh(b.x, b.y), pkh(b.z, b.w));
    }
    __syncthreads();   // S3 (covers Wsum + V)

    if (wid == 0 && tg == 0) {
        #pragma unroll
        for (int j = 0; j < 4; j++) {
            const int r = j * 8 + gq;
            float ssum = 0.f;
            #pragma unroll
            for (int w = 0; w < 8; w++) ssum += Wsum[w * 32 + r];
            Invs[r] = 1.0f / ssum;
        }
    }

    // ---- phase 3: ctx_w = P_w @ V_w (fp16; V B-frags via ldmatrix.trans) ----
    float ctx[2][8][4];
    #pragma unroll
    for (int mt = 0; mt < 2; mt++)
        #pragma unroll
        for (int ntd = 0; ntd < 8; ntd++)
            #pragma unroll
            for (int q = 0; q < 4; q++) ctx[mt][ntd][q] = 0.f;

    const int vrow = wid * 64 + (lane & 15);
    #pragma unroll
    for (int kt = 0; kt < 4; kt++) {          // k16 steps over warp's 64 keys
        uint32_t av[2][4];
        #pragma unroll
        for (int mt = 0; mt < 2; mt++) {
            av[mt][0] = ph[mt][2 * kt][0];
            av[mt][1] = ph[mt][2 * kt][1];
            av[mt][2] = ph[mt][2 * kt + 1][0];
            av[mt][3] = ph[mt][2 * kt + 1][1];
        }
        const uint32_t* vp0 = KV + (vrow + kt * 16) * KSP;
        #pragma unroll
        for (int ntd = 0; ntd < 8; ntd++) {
            uint32_t bf[2];
            const uint32_t sa = (uint32_t)__cvta_generic_to_shared(vp0 + ntd * 4);
            ldmx2t(bf[0], bf[1], sa);
            mma_f16(ctx[0][ntd], av[0], bf);
            mma_f16(ctx[1][ntd], av[1], bf);
        }
    }
    __syncthreads();   // S4: all V reads done; Invs published

    // ---- cross-warp ctx reduce through smem (aliased over KV) ----
    float* Cw = Cred + wid * 32 * CRS;
    #pragma unroll
    for (int mt = 0; mt < 2; mt++)
        #pragma unroll
        for (int ntd = 0; ntd < 8; ntd++) {
            *(float2*)(Cw + (mt * 16 + gq) * CRS + ntd * 8 + 2 * tg) =
                make_float2(ctx[mt][ntd][0], ctx[mt][ntd][1]);
            *(float2*)(Cw + (mt * 16 + gq + 8) * CRS + ntd * 8 + 2 * tg) =
                make_float2(ctx[mt][ntd][2], ctx[mt][ntd][3]);
        }
    __syncthreads();   // S5

    {
        const int row = tid & 31, c8 = (tid >> 5) * 8;
        float4 s0 = make_float4(0.f, 0.f, 0.f, 0.f);
        float4 s1 = make_float4(0.f, 0.f, 0.f, 0.f);
        #pragma unroll
        for (int w = 0; w < 8; w++) {
            const float* p = Cred + w * 32 * CRS + row * CRS + c8;
            const float4 t0 = *(const float4*)(p);
            const float4 t1 = *(const float4*)(p + 4);
            s0.x += t0.x; s0.y += t0.y; s0.z += t0.z; s0.w += t0.w;
            s1.x += t1.x; s1.y += t1.y; s1.z += t1.z; s1.w += t1.w;
        }
        const float iv = Invs[row];
        float* orow = out + ((size_t)gb * LQ + l0 + row) * NC + h * DH + c8;
        *(float4*)(orow)     = make_float4(s0.x * iv, s0.y * iv, s0.z * iv, s0.w * iv);
        *(float4*)(orow + 4) = make_float4(s1.x * iv, s1.y * iv, s1.z * iv, s1.w * iv);
    }
}

// ---------------------------------------------------------------------------
extern "C" void kernel_launch(void* const* d_in, const int* in_sizes, int n_in,
                              void* d_out, int out_size)
{
    (void)in_sizes; (void)n_in; (void)out_size;
    const float* hs   = (const float*)d_in[0];
    const float* mask = (const float*)d_in[1];
    const float* qw   = (const float*)d_in[2];
    const float* qb   = (const float*)d_in[3];
    const float* kw   = (const float*)d_in[4];
    const float* kb   = (const float*)d_in[5];
    const float* vw   = (const float*)d_in[6];
    const float* vb   = (const float*)d_in[7];
    float* out = (float*)d_out;

    float *qp, *kp, *vp, *wtp;
    cudaGetSymbolAddress((void**)&qp, g_q);
    cudaGetSymbolAddress((void**)&kp, g_k);
    cudaGetSymbolAddress((void**)&vp, g_v);
    cudaGetSymbolAddress((void**)&wtp, g_wt);

    dim3 tgrid(NC / 32, NC / 32, 12);
    wt_transpose_kernel<<<tgrid, dim3(32, 8)>>>(qw, kw, vw, wtp);

    const int gsmem = 4 * BUFF * (int)sizeof(float);   // 73728
    cudaFuncSetAttribute(qkv_mma_kernel,
                         cudaFuncAttributeMaxDynamicSharedMemorySize, gsmem);
    dim3 ggrid(NC / 128, MPG / 128, 12);
    qkv_mma_kernel<<<ggrid, 256, gsmem>>>(hs, wtp, qb, kb, vb, qp, kp, vp);

    const int asmem = ASM_U32 * (int)sizeof(uint32_t); // 82560
    cudaFuncSetAttribute(attn_flash_kernel,
                         cudaFuncAttributeMaxDynamicSharedMemorySize, asmem);
    dim3 agrid(LQ / QT, NG * NB * NH);
    attn_flash_kernel<<<agrid, 256, asmem>>>(qp, kp, vp, mask, out);
}

// round 13
// speedup vs baseline: 1.8627x; 1.4664x over previous
#include <cuda_runtime.h>
#include <cuda_fp16.h>
#include <cstdint>

#define NG   4
#define NB   4
#define LQ   512
#define NC   768
#define NH   12
#define DH   64
#define MPG  (NB*LQ)           // 2048 rows per group

// Half scratch (uint4 arrays force 16B alignment).
// q/k/v: [((g*NB+b)*NH+h)*LQ + l]*DH + dh  (halves)
__device__ uint4 g_qh[NG*NB*NH*LQ*DH/8];
__device__ uint4 g_kh[NG*NB*NH*LQ*DH/8];
__device__ uint4 g_vh[NG*NB*NH*LQ*DH/8];
// hs as half: [g][2048][768]
__device__ uint4 g_hsh[NG*MPG*NC/8];
// Transposed weights as half: [which*4+g][768][768] (row n = W[:,n])
__device__ uint4 g_wth[12*NC*NC/8];

__device__ __forceinline__ void mma_f16(float* d, const uint32_t* a, const uint32_t* b) {
    asm volatile(
        "mma.sync.aligned.m16n8k16.row.col.f32.f16.f16.f32 "
        "{%0,%1,%2,%3}, {%4,%5,%6,%7}, {%8,%9}, {%0,%1,%2,%3};"
        : "+f"(d[0]), "+f"(d[1]), "+f"(d[2]), "+f"(d[3])
        : "r"(a[0]), "r"(a[1]), "r"(a[2]), "r"(a[3]), "r"(b[0]), "r"(b[1]));
}

__device__ __forceinline__ void ldmx2t(uint32_t& b0, uint32_t& b1, uint32_t saddr) {
    asm volatile("ldmatrix.sync.aligned.m8n8.x2.trans.shared.b16 {%0,%1}, [%2];"
                 : "=r"(b0), "=r"(b1) : "r"(saddr));
}

__device__ __forceinline__ uint32_t pkh(float a, float b) {
    __half2 h = __floats2half2_rn(a, b);
    return *(uint32_t*)&h;
}

// FMA-pipe exp (avoids MUFU throughput ceiling). rel err ~2e-6.
__device__ __forceinline__ float fast_exp(float x) {
    float t = x * 1.4426950408889634f;
    t = fmaxf(t, -120.0f);
    const int  ei = __float2int_rn(t);
    const float f = t - (float)ei;
    float p =        1.3333558146e-3f;
    p = fmaf(p, f,   9.6181291076e-3f);
    p = fmaf(p, f,   5.5504108664e-2f);
    p = fmaf(p, f,   2.4022650695e-1f);
    p = fmaf(p, f,   6.9314718056e-1f);
    p = fmaf(p, f,   1.0f);
    return p * __int_as_float((ei + 127) << 23);
}

// ---------------------------------------------------------------------------
// hs -> half.  grid 6144, block 256 (4 floats/thread)
// ---------------------------------------------------------------------------
__global__ __launch_bounds__(256) void hs_convert_kernel(
    const float* __restrict__ hs, __half* __restrict__ outh)
{
    const int i = (blockIdx.x * 256 + threadIdx.x) * 4;
    const float4 v = *(const float4*)(hs + i);
    *(uint2*)(outh + i) = make_uint2(pkh(v.x, v.y), pkh(v.z, v.w));
}

// ---------------------------------------------------------------------------
// Weight transpose -> half: g_wth[w*4+g][n][k] = half(W_w,g[k][n]).
// grid (24,24,12), blk (32,8)
// ---------------------------------------------------------------------------
__global__ __launch_bounds__(256) void wt_transpose_kernel(
    const float* __restrict__ qw, const float* __restrict__ kw,
    const float* __restrict__ vw, __half* __restrict__ wt)
{
    __shared__ float tile[32][33];
    const int which = blockIdx.z >> 2, g = blockIdx.z & 3;
    const float* W = (which == 0 ? qw : which == 1 ? kw : vw) + (size_t)g * NC * NC;
    __half* WT = wt + (size_t)(which * 4 + g) * NC * NC;
    const int tx = threadIdx.x, ty = threadIdx.y;
    const int x = blockIdx.x * 32 + tx;
    const int y = blockIdx.y * 32 + ty;
    #pragma unroll
    for (int j = 0; j < 32; j += 8)
        tile[ty + j][tx] = W[(size_t)(y + j) * NC + x];
    __syncthreads();
    const int x2 = blockIdx.y * 32 + tx;
    const int y2 = blockIdx.x * 32 + ty;
    #pragma unroll
    for (int j = 0; j < 32; j += 8)
        WT[(size_t)(y2 + j) * NC + x2] = __float2half_rn(tile[tx][ty + j]);
}

// ---------------------------------------------------------------------------
// fp16 mma.sync QKV projection. 128x128 CTA tile, 8 warps (64x32 each),
// K in 12 chunks of 64. Store-ahead double-buffer pipeline.
// grid = (6, 16, 12), block = 256. Output q/k/v as half.
// ---------------------------------------------------------------------------
#define HKSP 36               // u32 stride per 64-half row
#define HBUF (128*HKSP)       // 4608 u32 per tile buffer

__global__ __launch_bounds__(256) void qkv_h_kernel(
    const __half* __restrict__ hsh, const __half* __restrict__ wth,
    const float* __restrict__ qb, const float* __restrict__ kb, const float* __restrict__ vb,
    __half* __restrict__ qp, __half* __restrict__ kp, __half* __restrict__ vp)
{
    extern __shared__ uint32_t smu[];
    uint32_t* As = smu;               // [2][HBUF]
    uint32_t* Bs = smu + 2 * HBUF;    // [2][HBUF]

    const int which = blockIdx.z >> 2, g = blockIdx.z & 3;
    const int m0 = blockIdx.y * 128, n0 = blockIdx.x * 128;
    const int tid = threadIdx.x, lane = tid & 31, wid = tid >> 5;
    const int wm = wid & 1, wn = wid >> 1;
    const int gq = lane >> 2, tg = lane & 3;

    const __half* Ag = hsh + (size_t)g * MPG * NC + (size_t)m0 * NC;
    const __half* Bg = wth + (size_t)(which * 4 + g) * NC * NC + (size_t)n0 * NC;
    const float*  bg = (which == 0 ? qb : which == 1 ? kb : vb) + (size_t)g * NC;
    __half*       op = (which == 0 ? qp : which == 1 ? kp : vp);

    float acc[4][4][4];
    #pragma unroll
    for (int i = 0; i < 4; i++)
        #pragma unroll
        for (int j = 0; j < 4; j++)
            #pragma unroll
            for (int q = 0; q < 4; q++) acc[i][j][q] = 0.f;

    const int lr = tid >> 1;          // 0..127 (row)
    const int lp = (tid & 1) * 32;    // half-offset within 64-half row

    uint4 pa[4], pb[4];
    // prologue: chunk 0 -> regs -> buf0; chunk 1 -> regs
    #pragma unroll
    for (int j = 0; j < 4; j++) {
        pa[j] = *(const uint4*)(Ag + (size_t)lr * NC + lp + j * 8);
        pb[j] = *(const uint4*)(Bg + (size_t)lr * NC + lp + j * 8);
    }
    #pragma unroll
    for (int j = 0; j < 4; j++) {
        *(uint4*)(As + lr * HKSP + lp / 2 + j * 4) = pa[j];
        *(uint4*)(Bs + lr * HKSP + lp / 2 + j * 4) = pb[j];
    }
    #pragma unroll
    for (int j = 0; j < 4; j++) {
        pa[j] = *(const uint4*)(Ag + (size_t)lr * NC + 64 + lp + j * 8);
        pb[j] = *(const uint4*)(Bg + (size_t)lr * NC + 64 + lp + j * 8);
    }
    __syncthreads();

    const int NCH = NC / 64;      // 12
    for (int c = 0; c < NCH; c++) {
        const int buf = c & 1;
        if (c + 1 < NCH) {
            const int nb = buf ^ 1;
            #pragma unroll
            for (int j = 0; j < 4; j++) {
                *(uint4*)(As + nb * HBUF + lr * HKSP + lp / 2 + j * 4) = pa[j];
                *(uint4*)(Bs + nb * HBUF + lr * HKSP + lp / 2 + j * 4) = pb[j];
            }
        }
        if (c + 2 < NCH) {
            const int kc = (c + 2) * 64;
            #pragma unroll
            for (int j = 0; j < 4; j++) {
                pa[j] = *(const uint4*)(Ag + (size_t)lr * NC + kc + lp + j * 8);
                pb[j] = *(const uint4*)(Bg + (size_t)lr * NC + kc + lp + j * 8);
            }
        }
        // compute chunk c: 4 k16-steps x 4 mt x 4 nt mma
        {
            const uint32_t* Ab = As + buf * HBUF + (wm * 64) * HKSP;
            const uint32_t* Bb = Bs + buf * HBUF + (wn * 32) * HKSP;
            #pragma unroll
            for (int kt = 0; kt < 4; kt++) {
                const int kk = kt * 8;
                uint32_t af[4][4], bf[4][2];
                #pragma unroll
                for (int mt = 0; mt < 4; mt++) {
                    const uint32_t* ap = Ab + (mt * 16 + gq) * HKSP + kk + tg;
                    af[mt][0] = ap[0];
                    af[mt][1] = ap[8 * HKSP];
                    af[mt][2] = ap[4];
                    af[mt][3] = ap[8 * HKSP + 4];
                }
                #pragma unroll
                for (int nt = 0; nt < 4; nt++) {
                    const uint32_t* bp = Bb + (nt * 8 + gq) * HKSP + kk + tg;
                    bf[nt][0] = bp[0];
                    bf[nt][1] = bp[4];
                }
                #pragma unroll
                for (int mt = 0; mt < 4; mt++)
                    #pragma unroll
                    for (int nt = 0; nt < 4; nt++)
                        mma_f16(acc[mt][nt], af[mt], bf[nt]);
            }
        }
        __syncthreads();
    }

    // epilogue: bias add, pack to half, head-major scatter
    #pragma unroll
    for (int mt = 0; mt < 4; mt++) {
        const int row0 = m0 + wm * 64 + mt * 16 + gq;
        #pragma unroll
        for (int half_ = 0; half_ < 2; half_++) {
            const int trow = row0 + half_ * 8;
            const int b = trow >> 9, l = trow & 511;
            #pragma unroll
            for (int nt = 0; nt < 4; nt++) {
                const int col = n0 + wn * 32 + nt * 8 + 2 * tg;
                const int h = col >> 6, dh = col & 63;
                const float2 bv = *(const float2*)(bg + col);
                const uint32_t o = pkh(acc[mt][nt][half_ * 2 + 0] + bv.x,
                                       acc[mt][nt][half_ * 2 + 1] + bv.y);
                *(uint32_t*)(op + ((((size_t)g * NB + b) * NH + h) * LQ + l) * DH + dh) = o;
            }
        }
    }
}

// ---------------------------------------------------------------------------
// Resident-KV flash attention, fp16 mma.sync (m16n8k16), 256 threads (8 warps).
// One CTA per (gbh, 32 queries); warp w owns keys [w*64, w*64+64).
// Q/K/V arrive as half (no conversion in the load loops).
// smem (u32 units): Qs[32][36] | mask[512]f | wmax[8][32]f | wsum[8][32]f |
//                   inv[32]f | KV[512][36] (Cred[8][32][68]f aliases KV)
// ---------------------------------------------------------------------------
#define QT   32
#define QSP  36
#define KSP  36
#define CRS  68
#define O_QS   0
#define O_MSK  1152
#define O_WMAX 1664
#define O_WSUM 1920
#define O_INV  2176
#define O_KV   2208
#define ASM_U32 (O_KV + 512*KSP)    // 20640 u32 = 82560 B

__global__ __launch_bounds__(256, 2) void attn_flash_kernel(
    const __half* __restrict__ qg, const __half* __restrict__ kg,
    const __half* __restrict__ vg, const float* __restrict__ mask,
    float* __restrict__ out)
{
    extern __shared__ uint32_t smu[];
    uint32_t* Qs   = smu + O_QS;
    float*    Msk  = (float*)(smu + O_MSK);
    float*    Wmax = (float*)(smu + O_WMAX);
    float*    Wsum = (float*)(smu + O_WSUM);
    float*    Invs = (float*)(smu + O_INV);
    uint32_t* KV   = smu + O_KV;
    float*    Cred = (float*)(smu + O_KV);   // alias (used after V is dead)

    const int gbh = blockIdx.y;
    const int l0  = blockIdx.x * QT;
    const int h   = gbh % NH;
    const int gb  = gbh / NH;
    const int tid  = threadIdx.x;
    const int lane = tid & 31;
    const int wid  = tid >> 5;          // 0..7
    const int gq = lane >> 2, tg = lane & 3;

    const __half* Q  = qg + (size_t)gbh * LQ * DH;
    const __half* K  = kg + (size_t)gbh * LQ * DH;
    const __half* V  = vg + (size_t)gbh * LQ * DH;
    const float*  mk = mask + (size_t)gb * LQ;

    // ---- loads: Q tile (1 uint4/thread), mask, full K (16 uint4/thread) ----
    {
        const int row = tid >> 3, j = tid & 7;     // 8 uint4 per 64-half row
        *(uint4*)(Qs + row * QSP + j * 4) =
            *(const uint4*)(Q + (size_t)(l0 + row) * DH + j * 8);
    }
    Msk[tid] = mk[tid];
    Msk[tid + 256] = mk[tid + 256];
    #pragma unroll
    for (int i = 0; i < 16; i++) {
        const int idx = i * 256 + tid;             // 4096 uint4, 8 per row
        const int r = idx >> 3, j = idx & 7;
        *(uint4*)(KV + r * KSP + j * 4) =
            *(const uint4*)(K + (size_t)r * DH + j * 8);
    }
    __syncthreads();   // S1

    // ---- Q fragments (m16n8k16) to registers ----
    uint32_t qf[2][4][4];
    #pragma unroll
    for (int ks = 0; ks < 4; ks++) {
        #pragma unroll
        for (int mt = 0; mt < 2; mt++) {
            const uint32_t* ap = Qs + (mt * 16 + gq) * QSP + ks * 8 + tg;
            qf[mt][ks][0] = ap[0];
            qf[mt][ks][1] = ap[8 * QSP];
            qf[mt][ks][2] = ap[4];
            qf[mt][ks][3] = ap[8 * QSP + 4];
        }
    }

    // ---- phase 1: S (32 x 64 per warp) in registers ----
    float sacc[2][8][4];
    #pragma unroll
    for (int mt = 0; mt < 2; mt++)
        #pragma unroll
        for (int nt = 0; nt < 8; nt++)
            #pragma unroll
            for (int q = 0; q < 4; q++) sacc[mt][nt][q] = 0.f;

    const uint32_t* Kb = KV + wid * 64 * KSP;
    #pragma unroll
    for (int ks = 0; ks < 4; ks++) {
        #pragma unroll
        for (int nt = 0; nt < 8; nt++) {
            uint32_t bf[2];
            const uint32_t* bp = Kb + (nt * 8 + gq) * KSP + ks * 8 + tg;
            bf[0] = bp[0];
            bf[1] = bp[4];
            mma_f16(sacc[0][nt], qf[0][ks], bf);
            mma_f16(sacc[1][nt], qf[1][ks], bf);
        }
    }

    // ---- scale + mask + local row max ----
    const float scale = 0.125f;
    float lm[2][2];
    lm[0][0] = lm[0][1] = lm[1][0] = lm[1][1] = -1e30f;
    #pragma unroll
    for (int mt = 0; mt < 2; mt++)
        #pragma unroll
        for (int nt = 0; nt < 8; nt++) {
            const int col = wid * 64 + nt * 8 + 2 * tg;
            const float m0v = Msk[col], m1v = Msk[col + 1];
            float* s = sacc[mt][nt];
            s[0] = fmaf(s[0], scale, m0v);
            s[1] = fmaf(s[1], scale, m1v);
            s[2] = fmaf(s[2], scale, m0v);
            s[3] = fmaf(s[3], scale, m1v);
            lm[mt][0] = fmaxf(lm[mt][0], fmaxf(s[0], s[1]));
            lm[mt][1] = fmaxf(lm[mt][1], fmaxf(s[2], s[3]));
        }
    #pragma unroll
    for (int mt = 0; mt < 2; mt++)
        #pragma unroll
        for (int hf = 0; hf < 2; hf++) {
            float m = lm[mt][hf];
            m = fmaxf(m, __shfl_xor_sync(0xFFFFFFFFu, m, 1));
            m = fmaxf(m, __shfl_xor_sync(0xFFFFFFFFu, m, 2));
            lm[mt][hf] = m;
        }
    if (tg == 0) {
        Wmax[wid * 32 + gq]      = lm[0][0];
        Wmax[wid * 32 + gq + 8]  = lm[0][1];
        Wmax[wid * 32 + gq + 16] = lm[1][0];
        Wmax[wid * 32 + gq + 24] = lm[1][1];
    }
    __syncthreads();   // S2 (all K reads done; Wmax published)

    // ---- global max, exp in regs -> packed half2 A-frags, local sum ----
    float gmax[2][2];
    #pragma unroll
    for (int mt = 0; mt < 2; mt++)
        #pragma unroll
        for (int hf = 0; hf < 2; hf++) {
            const int r = mt * 16 + gq + hf * 8;
            float m = -1e30f;
            #pragma unroll
            for (int w = 0; w < 8; w++) m = fmaxf(m, Wmax[w * 32 + r]);
            gmax[mt][hf] = m;
        }
    float ls[2][2] = {{0.f, 0.f}, {0.f, 0.f}};
    uint32_t ph[2][8][2];
    #pragma unroll
    for (int mt = 0; mt < 2; mt++)
        #pragma unroll
        for (int nt = 0; nt < 8; nt++) {
            const float* s = sacc[mt][nt];
            const float e0 = fast_exp(s[0] - gmax[mt][0]);
            const float e1 = fast_exp(s[1] - gmax[mt][0]);
            const float e2 = fast_exp(s[2] - gmax[mt][1]);
            const float e3 = fast_exp(s[3] - gmax[mt][1]);
            ls[mt][0] += e0 + e1;
            ls[mt][1] += e2 + e3;
            ph[mt][nt][0] = pkh(e0, e1);
            ph[mt][nt][1] = pkh(e2, e3);
        }
    #pragma unroll
    for (int mt = 0; mt < 2; mt++)
        #pragma unroll
        for (int hf = 0; hf < 2; hf++) {
            float v = ls[mt][hf];
            v += __shfl_xor_sync(0xFFFFFFFFu, v, 1);
            v += __shfl_xor_sync(0xFFFFFFFFu, v, 2);
            ls[mt][hf] = v;
        }
    if (tg == 0) {
        Wsum[wid * 32 + gq]      = ls[0][0];
        Wsum[wid * 32 + gq + 8]  = ls[0][1];
        Wsum[wid * 32 + gq + 16] = ls[1][0];
        Wsum[wid * 32 + gq + 24] = ls[1][1];
    }

    // ---- V load (half, same region; K is dead) ----
    #pragma unroll
    for (int i = 0; i < 16; i++) {
        const int idx = i * 256 + tid;
        const int r = idx >> 3, j = idx & 7;
        *(uint4*)(KV + r * KSP + j * 4) =
            *(const uint4*)(V + (size_t)r * DH + j * 8);
    }
    __syncthreads();   // S3 (covers Wsum + V)

    if (wid == 0 && tg == 0) {
        #pragma unroll
        for (int j = 0; j < 4; j++) {
            const int r = j * 8 + gq;
            float ssum = 0.f;
            #pragma unroll
            for (int w = 0; w < 8; w++) ssum += Wsum[w * 32 + r];
            Invs[r] = 1.0f / ssum;
        }
    }

    // ---- phase 3: ctx_w = P_w @ V_w (fp16; V B-frags via ldmatrix.trans) ----
    float ctx[2][8][4];
    #pragma unroll
    for (int mt = 0; mt < 2; mt++)
        #pragma unroll
        for (int ntd = 0; ntd < 8; ntd++)
            #pragma unroll
            for (int q = 0; q < 4; q++) ctx[mt][ntd][q] = 0.f;

    const int vrow = wid * 64 + (lane & 15);
    #pragma unroll
    for (int kt = 0; kt < 4; kt++) {          // k16 steps over warp's 64 keys
        uint32_t av[2][4];
        #pragma unroll
        for (int mt = 0; mt < 2; mt++) {
            av[mt][0] = ph[mt][2 * kt][0];
            av[mt][1] = ph[mt][2 * kt][1];
            av[mt][2] = ph[mt][2 * kt + 1][0];
            av[mt][3] = ph[mt][2 * kt + 1][1];
        }
        const uint32_t* vp0 = KV + (vrow + kt * 16) * KSP;
        #pragma unroll
        for (int ntd = 0; ntd < 8; ntd++) {
            uint32_t bf[2];
            const uint32_t sa = (uint32_t)__cvta_generic_to_shared(vp0 + ntd * 4);
            ldmx2t(bf[0], bf[1], sa);
            mma_f16(ctx[0][ntd], av[0], bf);
            mma_f16(ctx[1][ntd], av[1], bf);
        }
    }
    __syncthreads();   // S4: all V reads done; Invs published

    // ---- cross-warp ctx reduce through smem (aliased over KV) ----
    float* Cw = Cred + wid * 32 * CRS;
    #pragma unroll
    for (int mt = 0; mt < 2; mt++)
        #pragma unroll
        for (int ntd = 0; ntd < 8; ntd++) {
            *(float2*)(Cw + (mt * 16 + gq) * CRS + ntd * 8 + 2 * tg) =
                make_float2(ctx[mt][ntd][0], ctx[mt][ntd][1]);
            *(float2*)(Cw + (mt * 16 + gq + 8) * CRS + ntd * 8 + 2 * tg) =
                make_float2(ctx[mt][ntd][2], ctx[mt][ntd][3]);
        }
    __syncthreads();   // S5

    {
        const int row = tid & 31, c8 = (tid >> 5) * 8;
        float4 s0 = make_float4(0.f, 0.f, 0.f, 0.f);
        float4 s1 = make_float4(0.f, 0.f, 0.f, 0.f);
        #pragma unroll
        for (int w = 0; w < 8; w++) {
            const float* p = Cred + w * 32 * CRS + row * CRS + c8;
            const float4 t0 = *(const float4*)(p);
            const float4 t1 = *(const float4*)(p + 4);
            s0.x += t0.x; s0.y += t0.y; s0.z += t0.z; s0.w += t0.w;
            s1.x += t1.x; s1.y += t1.y; s1.z += t1.z; s1.w += t1.w;
        }
        const float iv = Invs[row];
        float* orow = out + ((size_t)gb * LQ + l0 + row) * NC + h * DH + c8;
        *(float4*)(orow)     = make_float4(s0.x * iv, s0.y * iv, s0.z * iv, s0.w * iv);
        *(float4*)(orow + 4) = make_float4(s1.x * iv, s1.y * iv, s1.z * iv, s1.w * iv);
    }
}

// ---------------------------------------------------------------------------
extern "C" void kernel_launch(void* const* d_in, const int* in_sizes, int n_in,
                              void* d_out, int out_size)
{
    (void)in_sizes; (void)n_in; (void)out_size;
    const float* hs   = (const float*)d_in[0];
    const float* mask = (const float*)d_in[1];
    const float* qw   = (const float*)d_in[2];
    const float* qb   = (const float*)d_in[3];
    const float* kw   = (const float*)d_in[4];
    const float* kb   = (const float*)d_in[5];
    const float* vw   = (const float*)d_in[6];
    const float* vb   = (const float*)d_in[7];
    float* out = (float*)d_out;

    void *qp, *kp, *vp, *wtp, *hsp;
    cudaGetSymbolAddress(&qp, g_qh);
    cudaGetSymbolAddress(&kp, g_kh);
    cudaGetSymbolAddress(&vp, g_vh);
    cudaGetSymbolAddress(&wtp, g_wth);
    cudaGetSymbolAddress(&hsp, g_hsh);

    hs_convert_kernel<<<NG * MPG * NC / 1024, 256>>>(hs, (__half*)hsp);

    dim3 tgrid(NC / 32, NC / 32, 12);
    wt_transpose_kernel<<<tgrid, dim3(32, 8)>>>(qw, kw, vw, (__half*)wtp);

    const int gsmem = 4 * HBUF * (int)sizeof(uint32_t);   // 73728
    cudaFuncSetAttribute(qkv_h_kernel,
                         cudaFuncAttributeMaxDynamicSharedMemorySize, gsmem);
    dim3 ggrid(NC / 128, MPG / 128, 12);
    qkv_h_kernel<<<ggrid, 256, gsmem>>>((const __half*)hsp, (const __half*)wtp,
                                        qb, kb, vb,
                                        (__half*)qp, (__half*)kp, (__half*)vp);

    const int asmem = ASM_U32 * (int)sizeof(uint32_t);    // 82560
    cudaFuncSetAttribute(attn_flash_kernel,
                         cudaFuncAttributeMaxDynamicSharedMemorySize, asmem);
    dim3 agrid(LQ / QT, NG * NB * NH);
    attn_flash_kernel<<<agrid, 256, asmem>>>((const __half*)qp, (const __half*)kp,
                                             (const __half*)vp, mask, out);
}

// round 14
// speedup vs baseline: 1.8874x; 1.0133x over previous
#include <cuda_runtime.h>
#include <cuda_fp16.h>
#include <cstdint>

#define NG   4
#define NB   4
#define LQ   512
#define NC   768
#define NH   12
#define DH   64
#define MPG  (NB*LQ)           // 2048 rows per group

// Half scratch (uint4 arrays force 16B alignment).
__device__ uint4 g_qh[NG*NB*NH*LQ*DH/8];
__device__ uint4 g_kh[NG*NB*NH*LQ*DH/8];
__device__ uint4 g_vh[NG*NB*NH*LQ*DH/8];
// hs as half: [g][2048][768]
__device__ uint4 g_hsh[NG*MPG*NC/8];
// Weights as half, ORIGINAL [k][n] layout: [which*4+g][768][768]
__device__ uint4 g_wh[12*NC*NC/8];

__device__ __forceinline__ void mma_f16(float* d, const uint32_t* a, const uint32_t* b) {
    asm volatile(
        "mma.sync.aligned.m16n8k16.row.col.f32.f16.f16.f32 "
        "{%0,%1,%2,%3}, {%4,%5,%6,%7}, {%8,%9}, {%0,%1,%2,%3};"
        : "+f"(d[0]), "+f"(d[1]), "+f"(d[2]), "+f"(d[3])
        : "r"(a[0]), "r"(a[1]), "r"(a[2]), "r"(a[3]), "r"(b[0]), "r"(b[1]));
}

__device__ __forceinline__ void ldmx2t(uint32_t& b0, uint32_t& b1, uint32_t saddr) {
    asm volatile("ldmatrix.sync.aligned.m8n8.x2.trans.shared.b16 {%0,%1}, [%2];"
                 : "=r"(b0), "=r"(b1) : "r"(saddr));
}
__device__ __forceinline__ void ldmx2(uint32_t& b0, uint32_t& b1, uint32_t saddr) {
    asm volatile("ldmatrix.sync.aligned.m8n8.x2.shared.b16 {%0,%1}, [%2];"
                 : "=r"(b0), "=r"(b1) : "r"(saddr));
}
__device__ __forceinline__ void ldmx4(uint32_t* d, uint32_t saddr) {
    asm volatile("ldmatrix.sync.aligned.m8n8.x4.shared.b16 {%0,%1,%2,%3}, [%4];"
                 : "=r"(d[0]), "=r"(d[1]), "=r"(d[2]), "=r"(d[3]) : "r"(saddr));
}

__device__ __forceinline__ uint32_t cvta_s(const void* p) {
    return (uint32_t)__cvta_generic_to_shared(p);
}

#define CP_ASYNC16(sa, g) \
    asm volatile("cp.async.cg.shared.global [%0], [%1], 16;" :: "r"(sa), "l"(g) : "memory")
#define CP_COMMIT() asm volatile("cp.async.commit_group;" ::: "memory")
#define CP_WAIT0()  asm volatile("cp.async.wait_group 0;" ::: "memory")

__device__ __forceinline__ uint32_t pkh(float a, float b) {
    __half2 h = __floats2half2_rn(a, b);
    return *(uint32_t*)&h;
}

// FMA-pipe exp (avoids MUFU throughput ceiling). rel err ~2e-6.
__device__ __forceinline__ float fast_exp(float x) {
    float t = x * 1.4426950408889634f;
    t = fmaxf(t, -120.0f);
    const int  ei = __float2int_rn(t);
    const float f = t - (float)ei;
    float p =        1.3333558146e-3f;
    p = fmaf(p, f,   9.6181291076e-3f);
    p = fmaf(p, f,   5.5504108664e-2f);
    p = fmaf(p, f,   2.4022650695e-1f);
    p = fmaf(p, f,   6.9314718056e-1f);
    p = fmaf(p, f,   1.0f);
    return p * __int_as_float((ei + 127) << 23);
}

// ---------------------------------------------------------------------------
// hs -> half.  grid 6144, block 256 (4 floats/thread)
// ---------------------------------------------------------------------------
__global__ __launch_bounds__(256) void hs_convert_kernel(
    const float* __restrict__ hs, __half* __restrict__ outh)
{
    const int i = (blockIdx.x * 256 + threadIdx.x) * 4;
    const float4 v = *(const float4*)(hs + i);
    *(uint2*)(outh + i) = make_uint2(pkh(v.x, v.y), pkh(v.z, v.w));
}

// ---------------------------------------------------------------------------
// W -> half, layout preserved [k][n]. grid (576, 12), block 256.
// ---------------------------------------------------------------------------
__global__ __launch_bounds__(256) void w_convert_kernel(
    const float* __restrict__ qw, const float* __restrict__ kw,
    const float* __restrict__ vw, __half* __restrict__ wh)
{
    const int which = blockIdx.y >> 2, g = blockIdx.y & 3;
    const float* W = (which == 0 ? qw : which == 1 ? kw : vw) + (size_t)g * NC * NC;
    __half* WH = wh + (size_t)blockIdx.y * NC * NC;
    const int i = (blockIdx.x * 256 + threadIdx.x) * 4;
    const float4 v = *(const float4*)(W + i);
    *(uint2*)(WH + i) = make_uint2(pkh(v.x, v.y), pkh(v.z, v.w));
}

// ---------------------------------------------------------------------------
// fp16 mma.sync QKV projection. 128x128 CTA tile, 8 warps (64x32 each),
// K in 12 chunks of 64. Store-ahead double-buffer pipeline.
// B kept k-major ([k][n]); B-frags via ldmatrix.x2.trans (same as attn V).
// grid = (6, 16, 12), block = 256. Output q/k/v as half.
// ---------------------------------------------------------------------------
#define ASTR 36               // u32 stride per 64-half A row
#define ABUF (128*ASTR)       // 4608 u32
#define BSTR 68               // u32 stride per 128-half B row (+pad)
#define BBUF (64*BSTR)        // 4352 u32
#define QSMEM_U32 (2*ABUF + 2*BBUF)   // 17920 u32 = 71680 B

__global__ __launch_bounds__(256) void qkv_h_kernel(
    const __half* __restrict__ hsh, const __half* __restrict__ wh,
    const float* __restrict__ qb, const float* __restrict__ kb, const float* __restrict__ vb,
    __half* __restrict__ qp, __half* __restrict__ kp, __half* __restrict__ vp)
{
    extern __shared__ uint32_t smu[];
    uint32_t* As = smu;               // [2][ABUF]
    uint32_t* Bs = smu + 2 * ABUF;    // [2][BBUF]

    const int which = blockIdx.z >> 2, g = blockIdx.z & 3;
    const int m0 = blockIdx.y * 128, n0 = blockIdx.x * 128;
    const int tid = threadIdx.x, lane = tid & 31, wid = tid >> 5;
    const int wm = wid & 1, wn = wid >> 1;
    const int gq = lane >> 2, tg = lane & 3;

    const __half* Ag = hsh + (size_t)g * MPG * NC + (size_t)m0 * NC;
    const __half* Bg = wh + (size_t)(which * 4 + g) * NC * NC + n0;  // [k][n]
    const float*  bg = (which == 0 ? qb : which == 1 ? kb : vb) + (size_t)g * NC;
    __half*       op = (which == 0 ? qp : which == 1 ? kp : vp);

    float acc[4][4][4];
    #pragma unroll
    for (int i = 0; i < 4; i++)
        #pragma unroll
        for (int j = 0; j < 4; j++)
            #pragma unroll
            for (int q = 0; q < 4; q++) acc[i][j][q] = 0.f;

    // A load mapping: 1024 uint4 (128 rows x 64 halves)
    const int alr = tid >> 1;          // 0..127 row
    const int alp = (tid & 1) * 32;    // half-offset
    // B load mapping: 1024 uint4 (64 k-rows x 128 n-halves)
    const int blr = tid >> 2;          // 0..63 k-row
    const int blj = (tid & 3) * 4;     // uint4 group within row (x4 iters)

    uint4 pa[4], pb[4];
    // prologue: chunk 0 -> regs -> buf0; chunk 1 -> regs
    #pragma unroll
    for (int j = 0; j < 4; j++) {
        pa[j] = *(const uint4*)(Ag + (size_t)alr * NC + alp + j * 8);
        pb[j] = *(const uint4*)(Bg + (size_t)blr * NC + (blj + j) * 8);
    }
    #pragma unroll
    for (int j = 0; j < 4; j++) {
        *(uint4*)(As + alr * ASTR + alp / 2 + j * 4) = pa[j];
        *(uint4*)(Bs + blr * BSTR + (blj + j) * 4) = pb[j];
    }
    #pragma unroll
    for (int j = 0; j < 4; j++) {
        pa[j] = *(const uint4*)(Ag + (size_t)alr * NC + 64 + alp + j * 8);
        pb[j] = *(const uint4*)(Bg + (size_t)(64 + blr) * NC + (blj + j) * 8);
    }
    __syncthreads();

    const int NCH = NC / 64;      // 12
    for (int c = 0; c < NCH; c++) {
        const int buf = c & 1;
        if (c + 1 < NCH) {
            const int nb = buf ^ 1;
            #pragma unroll
            for (int j = 0; j < 4; j++) {
                *(uint4*)(As + nb * ABUF + alr * ASTR + alp / 2 + j * 4) = pa[j];
                *(uint4*)(Bs + nb * BBUF + blr * BSTR + (blj + j) * 4) = pb[j];
            }
        }
        if (c + 2 < NCH) {
            const int kc = (c + 2) * 64;
            #pragma unroll
            for (int j = 0; j < 4; j++) {
                pa[j] = *(const uint4*)(Ag + (size_t)alr * NC + kc + alp + j * 8);
                pb[j] = *(const uint4*)(Bg + (size_t)(kc + blr) * NC + (blj + j) * 8);
            }
        }
        // compute chunk c: 4 k16-steps x 4 mt x 4 nt mma
        {
            const uint32_t* Ab = As + buf * ABUF + (wm * 64) * ASTR;
            const uint32_t* Bb = Bs + buf * BBUF;
            #pragma unroll
            for (int kt = 0; kt < 4; kt++) {
                const int kk = kt * 8;
                uint32_t af[4][4], bf[4][2];
                #pragma unroll
                for (int mt = 0; mt < 4; mt++) {
                    const uint32_t* ap = Ab + (mt * 16 + gq) * ASTR + kk + tg;
                    af[mt][0] = ap[0];
                    af[mt][1] = ap[8 * ASTR];
                    af[mt][2] = ap[4];
                    af[mt][3] = ap[8 * ASTR + 4];
                }
                #pragma unroll
                for (int nt = 0; nt < 4; nt++) {
                    const uint32_t sa = cvta_s(
                        Bb + (kt * 16 + (lane & 15)) * BSTR + wn * 16 + nt * 4);
                    ldmx2t(bf[nt][0], bf[nt][1], sa);
                }
                #pragma unroll
                for (int mt = 0; mt < 4; mt++)
                    #pragma unroll
                    for (int nt = 0; nt < 4; nt++)
                        mma_f16(acc[mt][nt], af[mt], bf[nt]);
            }
        }
        __syncthreads();
    }

    // epilogue: bias add, pack to half, head-major scatter
    #pragma unroll
    for (int mt = 0; mt < 4; mt++) {
        const int row0 = m0 + wm * 64 + mt * 16 + gq;
        #pragma unroll
        for (int half_ = 0; half_ < 2; half_++) {
            const int trow = row0 + half_ * 8;
            const int b = trow >> 9, l = trow & 511;
            #pragma unroll
            for (int nt = 0; nt < 4; nt++) {
                const int col = n0 + wn * 32 + nt * 8 + 2 * tg;
                const int h = col >> 6, dh = col & 63;
                const float2 bv = *(const float2*)(bg + col);
                const uint32_t o = pkh(acc[mt][nt][half_ * 2 + 0] + bv.x,
                                       acc[mt][nt][half_ * 2 + 1] + bv.y);
                *(uint32_t*)(op + ((((size_t)g * NB + b) * NH + h) * LQ + l) * DH + dh) = o;
            }
        }
    }
}

// ---------------------------------------------------------------------------
// Resident-KV flash attention, fp16 mma.sync (m16n8k16), 256 threads (8 warps).
// One CTA per (gbh, 32 queries); warp w owns keys [w*64, w*64+64).
// Q frags via ldmatrix.x4; K frags via ldmatrix.x2; V via cp.async + ldmatrix.
// smem (u32 units): Qs[32][36] | mask[512]f | wmax[8][32]f | wsum[8][32]f |
//                   inv[32]f | KV[512][36] (Cred[8][32][68]f aliases KV)
// ---------------------------------------------------------------------------
#define QT   32
#define QSP  36
#define KSP  36
#define CRS  68
#define O_QS   0
#define O_MSK  1152
#define O_WMAX 1664
#define O_WSUM 1920
#define O_INV  2176
#define O_KV   2208
#define ASM_U32 (O_KV + 512*KSP)    // 20640 u32 = 82560 B

__global__ __launch_bounds__(256, 2) void attn_flash_kernel(
    const __half* __restrict__ qg, const __half* __restrict__ kg,
    const __half* __restrict__ vg, const float* __restrict__ mask,
    float* __restrict__ out)
{
    extern __shared__ uint32_t smu[];
    uint32_t* Qs   = smu + O_QS;
    float*    Msk  = (float*)(smu + O_MSK);
    float*    Wmax = (float*)(smu + O_WMAX);
    float*    Wsum = (float*)(smu + O_WSUM);
    float*    Invs = (float*)(smu + O_INV);
    uint32_t* KV   = smu + O_KV;
    float*    Cred = (float*)(smu + O_KV);   // alias (used after V is dead)

    const int gbh = blockIdx.y;
    const int l0  = blockIdx.x * QT;
    const int h   = gbh % NH;
    const int gb  = gbh / NH;
    const int tid  = threadIdx.x;
    const int lane = tid & 31;
    const int wid  = tid >> 5;          // 0..7
    const int gq = lane >> 2, tg = lane & 3;

    const __half* Q  = qg + (size_t)gbh * LQ * DH;
    const __half* K  = kg + (size_t)gbh * LQ * DH;
    const __half* V  = vg + (size_t)gbh * LQ * DH;
    const float*  mk = mask + (size_t)gb * LQ;

    // ---- loads: Q tile (1 uint4/thread), mask, full K (16 uint4/thread) ----
    {
        const int row = tid >> 3, j = tid & 7;
        *(uint4*)(Qs + row * QSP + j * 4) =
            *(const uint4*)(Q + (size_t)(l0 + row) * DH + j * 8);
    }
    Msk[tid] = mk[tid];
    Msk[tid + 256] = mk[tid + 256];
    #pragma unroll
    for (int i = 0; i < 16; i++) {
        const int idx = i * 256 + tid;
        const int r = idx >> 3, j = idx & 7;
        *(uint4*)(KV + r * KSP + j * 4) =
            *(const uint4*)(K + (size_t)r * DH + j * 8);
    }
    __syncthreads();   // S1

    // ---- Q fragments via ldmatrix.x4 ----
    uint32_t qf[2][4][4];
    {
        const int qrow = (lane & 7) + ((lane >> 3) & 1) * 8;
        const int qcol = ((lane >> 4) & 1) * 4;
        #pragma unroll
        for (int mt = 0; mt < 2; mt++)
            #pragma unroll
            for (int ks = 0; ks < 4; ks++) {
                const uint32_t sa = cvta_s(
                    Qs + (mt * 16 + qrow) * QSP + ks * 8 + qcol);
                ldmx4(qf[mt][ks], sa);
            }
    }

    // ---- phase 1: S (32 x 64 per warp) in registers ----
    float sacc[2][8][4];
    #pragma unroll
    for (int mt = 0; mt < 2; mt++)
        #pragma unroll
        for (int nt = 0; nt < 8; nt++)
            #pragma unroll
            for (int q = 0; q < 4; q++) sacc[mt][nt][q] = 0.f;

    const uint32_t* Kb = KV + wid * 64 * KSP;
    const int krow = lane & 7;
    const int kcol = ((lane >> 3) & 1) * 4;
    #pragma unroll
    for (int ks = 0; ks < 4; ks++) {
        #pragma unroll
        for (int nt = 0; nt < 8; nt++) {
            uint32_t bf[2];
            const uint32_t sa = cvta_s(
                Kb + (nt * 8 + krow) * KSP + ks * 8 + kcol);
            ldmx2(bf[0], bf[1], sa);
            mma_f16(sacc[0][nt], qf[0][ks], bf);
            mma_f16(sacc[1][nt], qf[1][ks], bf);
        }
    }

    // ---- scale + mask + local row max ----
    const float scale = 0.125f;
    float lm[2][2];
    lm[0][0] = lm[0][1] = lm[1][0] = lm[1][1] = -1e30f;
    #pragma unroll
    for (int mt = 0; mt < 2; mt++)
        #pragma unroll
        for (int nt = 0; nt < 8; nt++) {
            const int col = wid * 64 + nt * 8 + 2 * tg;
            const float m0v = Msk[col], m1v = Msk[col + 1];
            float* s = sacc[mt][nt];
            s[0] = fmaf(s[0], scale, m0v);
            s[1] = fmaf(s[1], scale, m1v);
            s[2] = fmaf(s[2], scale, m0v);
            s[3] = fmaf(s[3], scale, m1v);
            lm[mt][0] = fmaxf(lm[mt][0], fmaxf(s[0], s[1]));
            lm[mt][1] = fmaxf(lm[mt][1], fmaxf(s[2], s[3]));
        }
    #pragma unroll
    for (int mt = 0; mt < 2; mt++)
        #pragma unroll
        for (int hf = 0; hf < 2; hf++) {
            float m = lm[mt][hf];
            m = fmaxf(m, __shfl_xor_sync(0xFFFFFFFFu, m, 1));
            m = fmaxf(m, __shfl_xor_sync(0xFFFFFFFFu, m, 2));
            lm[mt][hf] = m;
        }
    if (tg == 0) {
        Wmax[wid * 32 + gq]      = lm[0][0];
        Wmax[wid * 32 + gq + 8]  = lm[0][1];
        Wmax[wid * 32 + gq + 16] = lm[1][0];
        Wmax[wid * 32 + gq + 24] = lm[1][1];
    }
    __syncthreads();   // S2 (all K reads done; Wmax published)

    // ---- V load via cp.async (overlaps the exp work below) ----
    #pragma unroll
    for (int i = 0; i < 16; i++) {
        const int idx = i * 256 + tid;
        const int r = idx >> 3, j = idx & 7;
        CP_ASYNC16(cvta_s(KV + r * KSP + j * 4), V + (size_t)r * DH + j * 8);
    }
    CP_COMMIT();

    // ---- global max, exp in regs -> packed half2 A-frags, local sum ----
    float gmax[2][2];
    #pragma unroll
    for (int mt = 0; mt < 2; mt++)
        #pragma unroll
        for (int hf = 0; hf < 2; hf++) {
            const int r = mt * 16 + gq + hf * 8;
            float m = -1e30f;
            #pragma unroll
            for (int w = 0; w < 8; w++) m = fmaxf(m, Wmax[w * 32 + r]);
            gmax[mt][hf] = m;
        }
    float ls[2][2] = {{0.f, 0.f}, {0.f, 0.f}};
    uint32_t ph[2][8][2];
    #pragma unroll
    for (int mt = 0; mt < 2; mt++)
        #pragma unroll
        for (int nt = 0; nt < 8; nt++) {
            const float* s = sacc[mt][nt];
            const float e0 = fast_exp(s[0] - gmax[mt][0]);
            const float e1 = fast_exp(s[1] - gmax[mt][0]);
            const float e2 = fast_exp(s[2] - gmax[mt][1]);
            const float e3 = fast_exp(s[3] - gmax[mt][1]);
            ls[mt][0] += e0 + e1;
            ls[mt][1] += e2 + e3;
            ph[mt][nt][0] = pkh(e0, e1);
            ph[mt][nt][1] = pkh(e2, e3);
        }
    #pragma unroll
    for (int mt = 0; mt < 2; mt++)
        #pragma unroll
        for (int hf = 0; hf < 2; hf++) {
            float v = ls[mt][hf];
            v += __shfl_xor_sync(0xFFFFFFFFu, v, 1);
            v += __shfl_xor_sync(0xFFFFFFFFu, v, 2);
            ls[mt][hf] = v;
        }
    if (tg == 0) {
        Wsum[wid * 32 + gq]      = ls[0][0];
        Wsum[wid * 32 + gq + 8]  = ls[0][1];
        Wsum[wid * 32 + gq + 16] = ls[1][0];
        Wsum[wid * 32 + gq + 24] = ls[1][1];
    }

    CP_WAIT0();
    __syncthreads();   // S3 (covers Wsum + V)

    if (wid == 0 && tg == 0) {
        #pragma unroll
        for (int j = 0; j < 4; j++) {
            const int r = j * 8 + gq;
            float ssum = 0.f;
            #pragma unroll
            for (int w = 0; w < 8; w++) ssum += Wsum[w * 32 + r];
            Invs[r] = 1.0f / ssum;
        }
    }

    // ---- phase 3: ctx_w = P_w @ V_w (fp16; V B-frags via ldmatrix.trans) ----
    float ctx[2][8][4];
    #pragma unroll
    for (int mt = 0; mt < 2; mt++)
        #pragma unroll
        for (int ntd = 0; ntd < 8; ntd++)
            #pragma unroll
            for (int q = 0; q < 4; q++) ctx[mt][ntd][q] = 0.f;

    const int vrow = wid * 64 + (lane & 15);
    #pragma unroll
    for (int kt = 0; kt < 4; kt++) {
        uint32_t av[2][4];
        #pragma unroll
        for (int mt = 0; mt < 2; mt++) {
            av[mt][0] = ph[mt][2 * kt][0];
            av[mt][1] = ph[mt][2 * kt][1];
            av[mt][2] = ph[mt][2 * kt + 1][0];
            av[mt][3] = ph[mt][2 * kt + 1][1];
        }
        const uint32_t* vp0 = KV + (vrow + kt * 16) * KSP;
        #pragma unroll
        for (int ntd = 0; ntd < 8; ntd++) {
            uint32_t bf[2];
            const uint32_t sa = cvta_s(vp0 + ntd * 4);
            ldmx2t(bf[0], bf[1], sa);
            mma_f16(ctx[0][ntd], av[0], bf);
            mma_f16(ctx[1][ntd], av[1], bf);
        }
    }
    __syncthreads();   // S4: all V reads done; Invs published

    // ---- cross-warp ctx reduce through smem (aliased over KV) ----
    float* Cw = Cred + wid * 32 * CRS;
    #pragma unroll
    for (int mt = 0; mt < 2; mt++)
        #pragma unroll
        for (int ntd = 0; ntd < 8; ntd++) {
            *(float2*)(Cw + (mt * 16 + gq) * CRS + ntd * 8 + 2 * tg) =
                make_float2(ctx[mt][ntd][0], ctx[mt][ntd][1]);
            *(float2*)(Cw + (mt * 16 + gq + 8) * CRS + ntd * 8 + 2 * tg) =
                make_float2(ctx[mt][ntd][2], ctx[mt][ntd][3]);
        }
    __syncthreads();   // S5

    {
        const int row = tid & 31, c8 = (tid >> 5) * 8;
        float4 s0 = make_float4(0.f, 0.f, 0.f, 0.f);
        float4 s1 = make_float4(0.f, 0.f, 0.f, 0.f);
        #pragma unroll
        for (int w = 0; w < 8; w++) {
            const float* p = Cred + w * 32 * CRS + row * CRS + c8;
            const float4 t0 = *(const float4*)(p);
            const float4 t1 = *(const float4*)(p + 4);
            s0.x += t0.x; s0.y += t0.y; s0.z += t0.z; s0.w += t0.w;
            s1.x += t1.x; s1.y += t1.y; s1.z += t1.z; s1.w += t1.w;
        }
        const float iv = Invs[row];
        float* orow = out + ((size_t)gb * LQ + l0 + row) * NC + h * DH + c8;
        *(float4*)(orow)     = make_float4(s0.x * iv, s0.y * iv, s0.z * iv, s0.w * iv);
        *(float4*)(orow + 4) = make_float4(s1.x * iv, s1.y * iv, s1.z * iv, s1.w * iv);
    }
}

// ---------------------------------------------------------------------------
extern "C" void kernel_launch(void* const* d_in, const int* in_sizes, int n_in,
                              void* d_out, int out_size)
{
    (void)in_sizes; (void)n_in; (void)out_size;
    const float* hs   = (const float*)d_in[0];
    const float* mask = (const float*)d_in[1];
    const float* qw   = (const float*)d_in[2];
    const float* qb   = (const float*)d_in[3];
    const float* kw   = (const float*)d_in[4];
    const float* kb   = (const float*)d_in[5];
    const float* vw   = (const float*)d_in[6];
    const float* vb   = (const float*)d_in[7];
    float* out = (float*)d_out;

    void *qp, *kp, *vp, *wp, *hsp;
    cudaGetSymbolAddress(&qp, g_qh);
    cudaGetSymbolAddress(&kp, g_kh);
    cudaGetSymbolAddress(&vp, g_vh);
    cudaGetSymbolAddress(&wp, g_wh);
    cudaGetSymbolAddress(&hsp, g_hsh);

    hs_convert_kernel<<<NG * MPG * NC / 1024, 256>>>(hs, (__half*)hsp);

    dim3 wgrid(NC * NC / 1024, 12);
    w_convert_kernel<<<wgrid, 256>>>(qw, kw, vw, (__half*)wp);

    const int gsmem = QSMEM_U32 * (int)sizeof(uint32_t);  // 71680
    cudaFuncSetAttribute(qkv_h_kernel,
                         cudaFuncAttributeMaxDynamicSharedMemorySize, gsmem);
    dim3 ggrid(NC / 128, MPG / 128, 12);
    qkv_h_kernel<<<ggrid, 256, gsmem>>>((const __half*)hsp, (const __half*)wp,
                                        qb, kb, vb,
                                        (__half*)qp, (__half*)kp, (__half*)vp);

    const int asmem = ASM_U32 * (int)sizeof(uint32_t);    // 82560
    cudaFuncSetAttribute(attn_flash_kernel,
                         cudaFuncAttributeMaxDynamicSharedMemorySize, asmem);
    dim3 agrid(LQ / QT, NG * NB * NH);
    attn_flash_kernel<<<agrid, 256, asmem>>>((const __half*)qp, (const __half*)kp,
                                             (const __half*)vp, mask, out);
}

// round 15
// speedup vs baseline: 2.0702x; 1.0968x over previous
#include <cuda_runtime.h>
#include <cuda_fp16.h>
#include <cstdint>

#define NG   4
#define NB   4
#define LQ   512
#define NC   768
#define NH   12
#define DH   64
#define MPG  (NB*LQ)           // 2048 rows per group

// Half scratch (uint4 arrays force 16B alignment).
__device__ uint4 g_qh[NG*NB*NH*LQ*DH/8];
__device__ uint4 g_kh[NG*NB*NH*LQ*DH/8];
__device__ uint4 g_vh[NG*NB*NH*LQ*DH/8];
// hs as half: [g][2048][768]
__device__ uint4 g_hsh[NG*MPG*NC/8];
// Weights as half, ORIGINAL [k][n] layout: [which*4+g][768][768]
__device__ uint4 g_wh[12*NC*NC/8];

__device__ __forceinline__ void mma_f16(float* d, const uint32_t* a, const uint32_t* b) {
    asm volatile(
        "mma.sync.aligned.m16n8k16.row.col.f32.f16.f16.f32 "
        "{%0,%1,%2,%3}, {%4,%5,%6,%7}, {%8,%9}, {%0,%1,%2,%3};"
        : "+f"(d[0]), "+f"(d[1]), "+f"(d[2]), "+f"(d[3])
        : "r"(a[0]), "r"(a[1]), "r"(a[2]), "r"(a[3]), "r"(b[0]), "r"(b[1]));
}

__device__ __forceinline__ void ldmx2t(uint32_t& b0, uint32_t& b1, uint32_t saddr) {
    asm volatile("ldmatrix.sync.aligned.m8n8.x2.trans.shared.b16 {%0,%1}, [%2];"
                 : "=r"(b0), "=r"(b1) : "r"(saddr));
}
__device__ __forceinline__ void ldmx2(uint32_t& b0, uint32_t& b1, uint32_t saddr) {
    asm volatile("ldmatrix.sync.aligned.m8n8.x2.shared.b16 {%0,%1}, [%2];"
                 : "=r"(b0), "=r"(b1) : "r"(saddr));
}
__device__ __forceinline__ void ldmx4(uint32_t* d, uint32_t saddr) {
    asm volatile("ldmatrix.sync.aligned.m8n8.x4.shared.b16 {%0,%1,%2,%3}, [%4];"
                 : "=r"(d[0]), "=r"(d[1]), "=r"(d[2]), "=r"(d[3]) : "r"(saddr));
}

__device__ __forceinline__ uint32_t cvta_s(const void* p) {
    return (uint32_t)__cvta_generic_to_shared(p);
}

#define CP_ASYNC16(sa, g) \
    asm volatile("cp.async.cg.shared.global [%0], [%1], 16;" :: "r"(sa), "l"(g) : "memory")
#define CP_COMMIT() asm volatile("cp.async.commit_group;" ::: "memory")
#define CP_WAIT0()  asm volatile("cp.async.wait_group 0;" ::: "memory")
#define CP_WAIT1()  asm volatile("cp.async.wait_group 1;" ::: "memory")

__device__ __forceinline__ uint32_t pkh(float a, float b) {
    __half2 h = __floats2half2_rn(a, b);
    return *(uint32_t*)&h;
}

// FMA-pipe exp (avoids MUFU throughput ceiling). rel err ~2e-6.
__device__ __forceinline__ float fast_exp(float x) {
    float t = x * 1.4426950408889634f;
    t = fmaxf(t, -120.0f);
    const int  ei = __float2int_rn(t);
    const float f = t - (float)ei;
    float p =        1.3333558146e-3f;
    p = fmaf(p, f,   9.6181291076e-3f);
    p = fmaf(p, f,   5.5504108664e-2f);
    p = fmaf(p, f,   2.4022650695e-1f);
    p = fmaf(p, f,   6.9314718056e-1f);
    p = fmaf(p, f,   1.0f);
    return p * __int_as_float((ei + 127) << 23);
}

// ---------------------------------------------------------------------------
// hs -> half.  grid 6144, block 256 (4 floats/thread)
// ---------------------------------------------------------------------------
__global__ __launch_bounds__(256) void hs_convert_kernel(
    const float* __restrict__ hs, __half* __restrict__ outh)
{
    const int i = (blockIdx.x * 256 + threadIdx.x) * 4;
    const float4 v = *(const float4*)(hs + i);
    *(uint2*)(outh + i) = make_uint2(pkh(v.x, v.y), pkh(v.z, v.w));
}

// ---------------------------------------------------------------------------
// W -> half, layout preserved [k][n]. grid (576, 12), block 256.
// ---------------------------------------------------------------------------
__global__ __launch_bounds__(256) void w_convert_kernel(
    const float* __restrict__ qw, const float* __restrict__ kw,
    const float* __restrict__ vw, __half* __restrict__ wh)
{
    const int which = blockIdx.y >> 2, g = blockIdx.y & 3;
    const float* W = (which == 0 ? qw : which == 1 ? kw : vw) + (size_t)g * NC * NC;
    __half* WH = wh + (size_t)blockIdx.y * NC * NC;
    const int i = (blockIdx.x * 256 + threadIdx.x) * 4;
    const float4 v = *(const float4*)(W + i);
    *(uint2*)(WH + i) = make_uint2(pkh(v.x, v.y), pkh(v.z, v.w));
}

// ---------------------------------------------------------------------------
// fp16 mma.sync QKV projection (unchanged from R13).
// ---------------------------------------------------------------------------
#define ASTR 36               // u32 stride per 64-half A row
#define ABUF (128*ASTR)       // 4608 u32
#define BSTR 68               // u32 stride per 128-half B row (+pad)
#define BBUF (64*BSTR)        // 4352 u32
#define QSMEM_U32 (2*ABUF + 2*BBUF)   // 17920 u32 = 71680 B

__global__ __launch_bounds__(256) void qkv_h_kernel(
    const __half* __restrict__ hsh, const __half* __restrict__ wh,
    const float* __restrict__ qb, const float* __restrict__ kb, const float* __restrict__ vb,
    __half* __restrict__ qp, __half* __restrict__ kp, __half* __restrict__ vp)
{
    extern __shared__ uint32_t smu[];
    uint32_t* As = smu;               // [2][ABUF]
    uint32_t* Bs = smu + 2 * ABUF;    // [2][BBUF]

    const int which = blockIdx.z >> 2, g = blockIdx.z & 3;
    const int m0 = blockIdx.y * 128, n0 = blockIdx.x * 128;
    const int tid = threadIdx.x, lane = tid & 31, wid = tid >> 5;
    const int wm = wid & 1, wn = wid >> 1;
    const int gq = lane >> 2, tg = lane & 3;

    const __half* Ag = hsh + (size_t)g * MPG * NC + (size_t)m0 * NC;
    const __half* Bg = wh + (size_t)(which * 4 + g) * NC * NC + n0;  // [k][n]
    const float*  bg = (which == 0 ? qb : which == 1 ? kb : vb) + (size_t)g * NC;
    __half*       op = (which == 0 ? qp : which == 1 ? kp : vp);

    float acc[4][4][4];
    #pragma unroll
    for (int i = 0; i < 4; i++)
        #pragma unroll
        for (int j = 0; j < 4; j++)
            #pragma unroll
            for (int q = 0; q < 4; q++) acc[i][j][q] = 0.f;

    const int alr = tid >> 1;
    const int alp = (tid & 1) * 32;
    const int blr = tid >> 2;
    const int blj = (tid & 3) * 4;

    uint4 pa[4], pb[4];
    #pragma unroll
    for (int j = 0; j < 4; j++) {
        pa[j] = *(const uint4*)(Ag + (size_t)alr * NC + alp + j * 8);
        pb[j] = *(const uint4*)(Bg + (size_t)blr * NC + (blj + j) * 8);
    }
    #pragma unroll
    for (int j = 0; j < 4; j++) {
        *(uint4*)(As + alr * ASTR + alp / 2 + j * 4) = pa[j];
        *(uint4*)(Bs + blr * BSTR + (blj + j) * 4) = pb[j];
    }
    #pragma unroll
    for (int j = 0; j < 4; j++) {
        pa[j] = *(const uint4*)(Ag + (size_t)alr * NC + 64 + alp + j * 8);
        pb[j] = *(const uint4*)(Bg + (size_t)(64 + blr) * NC + (blj + j) * 8);
    }
    __syncthreads();

    const int NCH = NC / 64;      // 12
    for (int c = 0; c < NCH; c++) {
        const int buf = c & 1;
        if (c + 1 < NCH) {
            const int nb = buf ^ 1;
            #pragma unroll
            for (int j = 0; j < 4; j++) {
                *(uint4*)(As + nb * ABUF + alr * ASTR + alp / 2 + j * 4) = pa[j];
                *(uint4*)(Bs + nb * BBUF + blr * BSTR + (blj + j) * 4) = pb[j];
            }
        }
        if (c + 2 < NCH) {
            const int kc = (c + 2) * 64;
            #pragma unroll
            for (int j = 0; j < 4; j++) {
                pa[j] = *(const uint4*)(Ag + (size_t)alr * NC + kc + alp + j * 8);
                pb[j] = *(const uint4*)(Bg + (size_t)(kc + blr) * NC + (blj + j) * 8);
            }
        }
        {
            const uint32_t* Ab = As + buf * ABUF + (wm * 64) * ASTR;
            const uint32_t* Bb = Bs + buf * BBUF;
            #pragma unroll
            for (int kt = 0; kt < 4; kt++) {
                const int kk = kt * 8;
                uint32_t af[4][4], bf[4][2];
                #pragma unroll
                for (int mt = 0; mt < 4; mt++) {
                    const uint32_t* ap = Ab + (mt * 16 + gq) * ASTR + kk + tg;
                    af[mt][0] = ap[0];
                    af[mt][1] = ap[8 * ASTR];
                    af[mt][2] = ap[4];
                    af[mt][3] = ap[8 * ASTR + 4];
                }
                #pragma unroll
                for (int nt = 0; nt < 4; nt++) {
                    const uint32_t sa = cvta_s(
                        Bb + (kt * 16 + (lane & 15)) * BSTR + wn * 16 + nt * 4);
                    ldmx2t(bf[nt][0], bf[nt][1], sa);
                }
                #pragma unroll
                for (int mt = 0; mt < 4; mt++)
                    #pragma unroll
                    for (int nt = 0; nt < 4; nt++)
                        mma_f16(acc[mt][nt], af[mt], bf[nt]);
            }
        }
        __syncthreads();
    }

    #pragma unroll
    for (int mt = 0; mt < 4; mt++) {
        const int row0 = m0 + wm * 64 + mt * 16 + gq;
        #pragma unroll
        for (int half_ = 0; half_ < 2; half_++) {
            const int trow = row0 + half_ * 8;
            const int b = trow >> 9, l = trow & 511;
            #pragma unroll
            for (int nt = 0; nt < 4; nt++) {
                const int col = n0 + wn * 32 + nt * 8 + 2 * tg;
                const int h = col >> 6, dh = col & 63;
                const float2 bv = *(const float2*)(bg + col);
                const uint32_t o = pkh(acc[mt][nt][half_ * 2 + 0] + bv.x,
                                       acc[mt][nt][half_ * 2 + 1] + bv.y);
                *(uint32_t*)(op + ((((size_t)g * NB + b) * NH + h) * LQ + l) * DH + dh) = o;
            }
        }
    }
}

// ---------------------------------------------------------------------------
// Online-softmax flash attention, fp16 mma.sync, 256 threads (8 warps).
// One CTA per (gbh, 128 queries). Warp w owns query rows [w*16, w*16+16) for
// ALL 512 keys -> zero cross-warp reductions. KV streamed in 8 chunks of 64
// keys via cp.async 3-stage ring; 1 __syncthreads per chunk.
// smem (u32): Q[128][36] | mask[512]f | 3 x (K[64][36] + V[64][36])
// ---------------------------------------------------------------------------
#define FQT  128
#define FSP  36                       // u32 stride per 64-half row
#define FO_Q   0
#define FO_MSK (FQT*FSP)              // 4608
#define FO_KV  (FO_MSK + 512)         // 5120
#define FKV_B  (2*64*FSP)             // 4608 u32 per ring buffer (K then V)
#define FASM_U32 (FO_KV + 3*FKV_B)    // 18944 u32 = 75776 B

__global__ __launch_bounds__(256, 2) void attn_flash_kernel(
    const __half* __restrict__ qg, const __half* __restrict__ kg,
    const __half* __restrict__ vg, const float* __restrict__ mask,
    float* __restrict__ out)
{
    extern __shared__ uint32_t smu[];
    uint32_t* Qs  = smu + FO_Q;
    float*    Msk = (float*)(smu + FO_MSK);
    uint32_t* KVr = smu + FO_KV;

    const int gbh = blockIdx.y;
    const int l0q = blockIdx.x * FQT;
    const int h   = gbh % NH;
    const int gb  = gbh / NH;
    const int tid  = threadIdx.x;
    const int lane = tid & 31;
    const int wid  = tid >> 5;          // 0..7
    const int gq = lane >> 2, tg = lane & 3;

    const __half* Q  = qg + (size_t)gbh * LQ * DH + (size_t)l0q * DH;
    const __half* K  = kg + (size_t)gbh * LQ * DH;
    const __half* V  = vg + (size_t)gbh * LQ * DH;
    const float*  mk = mask + (size_t)gb * LQ;

    // ---- stage Q tile + mask (plain stores; covered by first loop sync) ----
    #pragma unroll
    for (int i = 0; i < 4; i++) {
        const int idx = i * 256 + tid;
        const int r = idx >> 3, j = idx & 7;
        *(uint4*)(Qs + r * FSP + j * 4) =
            *(const uint4*)(Q + (size_t)r * DH + j * 8);
    }
    Msk[tid] = mk[tid];
    Msk[tid + 256] = mk[tid + 256];

    // ---- cp.async prologue: chunks 0,1 -> buffers 0,1 ----
    const int clr = tid >> 2;           // 0..63 key-row within chunk
    const int clj = (tid & 3) * 2;      // 2 uint4 groups per tensor per thread
    #pragma unroll
    for (int pc = 0; pc < 2; pc++) {
        uint32_t* B = KVr + pc * FKV_B;
        #pragma unroll
        for (int j = 0; j < 2; j++) {
            CP_ASYNC16(cvta_s(B + clr * FSP + (clj + j) * 4),
                       K + (size_t)(pc * 64 + clr) * DH + (clj + j) * 8);
            CP_ASYNC16(cvta_s(B + 64 * FSP + clr * FSP + (clj + j) * 4),
                       V + (size_t)(pc * 64 + clr) * DH + (clj + j) * 8);
        }
        CP_COMMIT();
    }

    // ---- Q fragments via ldmatrix.x4 (after first sync) ----
    uint32_t qf[4][4];
    float ctx[8][4];
    #pragma unroll
    for (int ntd = 0; ntd < 8; ntd++)
        #pragma unroll
        for (int q = 0; q < 4; q++) ctx[ntd][q] = 0.f;
    float m0 = -1e30f, m1 = -1e30f, sl0 = 0.f, sl1 = 0.f;

    const float scale = 0.125f;
    const int qrow = (lane & 7) + ((lane >> 3) & 1) * 8;
    const int qcol = ((lane >> 4) & 1) * 4;
    const int krow = lane & 7;
    const int kcol = ((lane >> 3) & 1) * 4;
    bool qf_loaded = false;

    for (int c = 0; c < 8; c++) {
        if (c < 7) { CP_WAIT1(); } else { CP_WAIT0(); }
        __syncthreads();                    // chunk c resident in buf c%3

        // prefetch chunk c+2 into buf (c+2)%3 (freed: compute c-1 done)
        if (c + 2 < 8) {
            uint32_t* B = KVr + ((c + 2) % 3) * FKV_B;
            #pragma unroll
            for (int j = 0; j < 2; j++) {
                CP_ASYNC16(cvta_s(B + clr * FSP + (clj + j) * 4),
                           K + (size_t)((c + 2) * 64 + clr) * DH + (clj + j) * 8);
                CP_ASYNC16(cvta_s(B + 64 * FSP + clr * FSP + (clj + j) * 4),
                           V + (size_t)((c + 2) * 64 + clr) * DH + (clj + j) * 8);
            }
            CP_COMMIT();
        }

        if (!qf_loaded) {                   // once, after Q staged + synced
            #pragma unroll
            for (int ks = 0; ks < 4; ks++)
                ldmx4(qf[ks], cvta_s(Qs + (wid * 16 + qrow) * FSP + ks * 8 + qcol));
            qf_loaded = true;
        }

        const uint32_t* Kb = KVr + (c % 3) * FKV_B;
        const uint32_t* Vb = Kb + 64 * FSP;

        // ---- QK^T: 16 queries x 64 keys ----
        float s[8][4];
        #pragma unroll
        for (int nt = 0; nt < 8; nt++)
            #pragma unroll
            for (int q = 0; q < 4; q++) s[nt][q] = 0.f;
        #pragma unroll
        for (int ks = 0; ks < 4; ks++)
            #pragma unroll
            for (int nt = 0; nt < 8; nt++) {
                uint32_t bf[2];
                ldmx2(bf[0], bf[1],
                      cvta_s(Kb + (nt * 8 + krow) * FSP + ks * 8 + kcol));
                mma_f16(s[nt], qf[ks], bf);
            }

        // ---- scale + mask + chunk row max ----
        float cm0 = -1e30f, cm1 = -1e30f;
        #pragma unroll
        for (int nt = 0; nt < 8; nt++) {
            const int col = c * 64 + nt * 8 + 2 * tg;
            const float mv0 = Msk[col], mv1 = Msk[col + 1];
            s[nt][0] = fmaf(s[nt][0], scale, mv0);
            s[nt][1] = fmaf(s[nt][1], scale, mv1);
            s[nt][2] = fmaf(s[nt][2], scale, mv0);
            s[nt][3] = fmaf(s[nt][3], scale, mv1);
            cm0 = fmaxf(cm0, fmaxf(s[nt][0], s[nt][1]));
            cm1 = fmaxf(cm1, fmaxf(s[nt][2], s[nt][3]));
        }
        cm0 = fmaxf(cm0, __shfl_xor_sync(0xFFFFFFFFu, cm0, 1));
        cm0 = fmaxf(cm0, __shfl_xor_sync(0xFFFFFFFFu, cm0, 2));
        cm1 = fmaxf(cm1, __shfl_xor_sync(0xFFFFFFFFu, cm1, 1));
        cm1 = fmaxf(cm1, __shfl_xor_sync(0xFFFFFFFFu, cm1, 2));

        // ---- online rescale ----
        const float nm0 = fmaxf(m0, cm0), nm1 = fmaxf(m1, cm1);
        const float f0 = fast_exp(m0 - nm0), f1 = fast_exp(m1 - nm1);
        m0 = nm0; m1 = nm1;

        // ---- exp -> packed half2 A-frags, chunk sums ----
        uint32_t ph[8][2];
        float cs0 = 0.f, cs1 = 0.f;
        #pragma unroll
        for (int nt = 0; nt < 8; nt++) {
            const float e0 = fast_exp(s[nt][0] - nm0);
            const float e1 = fast_exp(s[nt][1] - nm0);
            const float e2 = fast_exp(s[nt][2] - nm1);
            const float e3 = fast_exp(s[nt][3] - nm1);
            cs0 += e0 + e1;
            cs1 += e2 + e3;
            ph[nt][0] = pkh(e0, e1);
            ph[nt][1] = pkh(e2, e3);
        }
        cs0 += __shfl_xor_sync(0xFFFFFFFFu, cs0, 1);
        cs0 += __shfl_xor_sync(0xFFFFFFFFu, cs0, 2);
        cs1 += __shfl_xor_sync(0xFFFFFFFFu, cs1, 1);
        cs1 += __shfl_xor_sync(0xFFFFFFFFu, cs1, 2);
        sl0 = sl0 * f0 + cs0;
        sl1 = sl1 * f1 + cs1;

        #pragma unroll
        for (int ntd = 0; ntd < 8; ntd++) {
            ctx[ntd][0] *= f0; ctx[ntd][1] *= f0;
            ctx[ntd][2] *= f1; ctx[ntd][3] *= f1;
        }

        // ---- PV: P(16x64) @ V(64x64) ----
        #pragma unroll
        for (int kt = 0; kt < 4; kt++) {
            uint32_t av[4];
            av[0] = ph[2 * kt][0];
            av[1] = ph[2 * kt][1];
            av[2] = ph[2 * kt + 1][0];
            av[3] = ph[2 * kt + 1][1];
            const uint32_t* vp0 = Vb + (kt * 16 + (lane & 15)) * FSP;
            #pragma unroll
            for (int ntd = 0; ntd < 8; ntd++) {
                uint32_t bf[2];
                ldmx2t(bf[0], bf[1], cvta_s(vp0 + ntd * 4));
                mma_f16(ctx[ntd], av, bf);
            }
        }
    }

    // ---- epilogue: normalize, write out ----
    const float iv0 = 1.0f / sl0, iv1 = 1.0f / sl1;
    const size_t row0 = (size_t)gb * LQ + l0q + wid * 16 + gq;
    const int colo = h * DH + 2 * tg;
    #pragma unroll
    for (int ntd = 0; ntd < 8; ntd++) {
        *(float2*)(out + row0 * NC + colo + ntd * 8) =
            make_float2(ctx[ntd][0] * iv0, ctx[ntd][1] * iv0);
        *(float2*)(out + (row0 + 8) * NC + colo + ntd * 8) =
            make_float2(ctx[ntd][2] * iv1, ctx[ntd][3] * iv1);
    }
}

// ---------------------------------------------------------------------------
extern "C" void kernel_launch(void* const* d_in, const int* in_sizes, int n_in,
                              void* d_out, int out_size)
{
    (void)in_sizes; (void)n_in; (void)out_size;
    const float* hs   = (const float*)d_in[0];
    const float* mask = (const float*)d_in[1];
    const float* qw   = (const float*)d_in[2];
    const float* qb   = (const float*)d_in[3];
    const float* kw   = (const float*)d_in[4];
    const float* kb   = (const float*)d_in[5];
    const float* vw   = (const float*)d_in[6];
    const float* vb   = (const float*)d_in[7];
    float* out = (float*)d_out;

    void *qp, *kp, *vp, *wp, *hsp;
    cudaGetSymbolAddress(&qp, g_qh);
    cudaGetSymbolAddress(&kp, g_kh);
    cudaGetSymbolAddress(&vp, g_vh);
    cudaGetSymbolAddress(&wp, g_wh);
    cudaGetSymbolAddress(&hsp, g_hsh);

    hs_convert_kernel<<<NG * MPG * NC / 1024, 256>>>(hs, (__half*)hsp);

    dim3 wgrid(NC * NC / 1024, 12);
    w_convert_kernel<<<wgrid, 256>>>(qw, kw, vw, (__half*)wp);

    const int gsmem = QSMEM_U32 * (int)sizeof(uint32_t);  // 71680
    cudaFuncSetAttribute(qkv_h_kernel,
                         cudaFuncAttributeMaxDynamicSharedMemorySize, gsmem);
    dim3 ggrid(NC / 128, MPG / 128, 12);
    qkv_h_kernel<<<ggrid, 256, gsmem>>>((const __half*)hsp, (const __half*)wp,
                                        qb, kb, vb,
                                        (__half*)qp, (__half*)kp, (__half*)vp);

    const int asmem = FASM_U32 * (int)sizeof(uint32_t);   // 75776
    cudaFuncSetAttribute(attn_flash_kernel,
                         cudaFuncAttributeMaxDynamicSharedMemorySize, asmem);
    dim3 agrid(LQ / FQT, NG * NB * NH);
    attn_flash_kernel<<<agrid, 256, asmem>>>((const __half*)qp, (const __half*)kp,
                                             (const __half*)vp, mask, out);
}

// round 16
// speedup vs baseline: 2.1868x; 1.0563x over previous
#include <cuda_runtime.h>
#include <cuda_fp16.h>
#include <cstdint>

#define NG   4
#define NB   4
#define LQ   512
#define NC   768
#define NH   12
#define DH   64
#define MPG  (NB*LQ)           // 2048 rows per group

// Half scratch (uint4 arrays force 16B alignment).
__device__ uint4 g_qh[NG*NB*NH*LQ*DH/8];
__device__ uint4 g_kh[NG*NB*NH*LQ*DH/8];
__device__ uint4 g_vh[NG*NB*NH*LQ*DH/8];
// hs as half: [g][2048][768]
__device__ uint4 g_hsh[NG*MPG*NC/8];
// Weights as half, ORIGINAL [k][n] layout: [which*4+g][768][768]
__device__ uint4 g_wh[12*NC*NC/8];

__device__ __forceinline__ void mma_f16(float* d, const uint32_t* a, const uint32_t* b) {
    asm volatile(
        "mma.sync.aligned.m16n8k16.row.col.f32.f16.f16.f32 "
        "{%0,%1,%2,%3}, {%4,%5,%6,%7}, {%8,%9}, {%0,%1,%2,%3};"
        : "+f"(d[0]), "+f"(d[1]), "+f"(d[2]), "+f"(d[3])
        : "r"(a[0]), "r"(a[1]), "r"(a[2]), "r"(a[3]), "r"(b[0]), "r"(b[1]));
}

__device__ __forceinline__ void ldmx4(uint32_t* d, uint32_t saddr) {
    asm volatile("ldmatrix.sync.aligned.m8n8.x4.shared.b16 {%0,%1,%2,%3}, [%4];"
                 : "=r"(d[0]), "=r"(d[1]), "=r"(d[2]), "=r"(d[3]) : "r"(saddr));
}
__device__ __forceinline__ void ldmx4t(uint32_t* d, uint32_t saddr) {
    asm volatile("ldmatrix.sync.aligned.m8n8.x4.trans.shared.b16 {%0,%1,%2,%3}, [%4];"
                 : "=r"(d[0]), "=r"(d[1]), "=r"(d[2]), "=r"(d[3]) : "r"(saddr));
}

__device__ __forceinline__ uint32_t cvta_s(const void* p) {
    return (uint32_t)__cvta_generic_to_shared(p);
}

#define CP_ASYNC16(sa, g) \
    asm volatile("cp.async.cg.shared.global [%0], [%1], 16;" :: "r"(sa), "l"(g) : "memory")
#define CP_COMMIT() asm volatile("cp.async.commit_group;" ::: "memory")
#define CP_WAIT0()  asm volatile("cp.async.wait_group 0;" ::: "memory")
#define CP_WAIT1()  asm volatile("cp.async.wait_group 1;" ::: "memory")

__device__ __forceinline__ uint32_t pkh(float a, float b) {
    __half2 h = __floats2half2_rn(a, b);
    return *(uint32_t*)&h;
}

// FMA-pipe exp (avoids MUFU throughput ceiling). rel err ~2e-6.
__device__ __forceinline__ float fast_exp(float x) {
    float t = x * 1.4426950408889634f;
    t = fmaxf(t, -120.0f);
    const int  ei = __float2int_rn(t);
    const float f = t - (float)ei;
    float p =        1.3333558146e-3f;
    p = fmaf(p, f,   9.6181291076e-3f);
    p = fmaf(p, f,   5.5504108664e-2f);
    p = fmaf(p, f,   2.4022650695e-1f);
    p = fmaf(p, f,   6.9314718056e-1f);
    p = fmaf(p, f,   1.0f);
    return p * __int_as_float((ei + 127) << 23);
}

// ---------------------------------------------------------------------------
// hs -> half.  grid 6144, block 256 (4 floats/thread)
// ---------------------------------------------------------------------------
__global__ __launch_bounds__(256) void hs_convert_kernel(
    const float* __restrict__ hs, __half* __restrict__ outh)
{
    const int i = (blockIdx.x * 256 + threadIdx.x) * 4;
    const float4 v = *(const float4*)(hs + i);
    *(uint2*)(outh + i) = make_uint2(pkh(v.x, v.y), pkh(v.z, v.w));
}

// ---------------------------------------------------------------------------
// W -> half, layout preserved [k][n]. grid (576, 12), block 256.
// ---------------------------------------------------------------------------
__global__ __launch_bounds__(256) void w_convert_kernel(
    const float* __restrict__ qw, const float* __restrict__ kw,
    const float* __restrict__ vw, __half* __restrict__ wh)
{
    const int which = blockIdx.y >> 2, g = blockIdx.y & 3;
    const float* W = (which == 0 ? qw : which == 1 ? kw : vw) + (size_t)g * NC * NC;
    __half* WH = wh + (size_t)blockIdx.y * NC * NC;
    const int i = (blockIdx.x * 256 + threadIdx.x) * 4;
    const float4 v = *(const float4*)(W + i);
    *(uint2*)(WH + i) = make_uint2(pkh(v.x, v.y), pkh(v.z, v.w));
}

// ---------------------------------------------------------------------------
// fp16 mma.sync QKV projection. 128x128 CTA tile, 8 warps (64x32 each),
// K in 12 chunks of 64. cp.async double-buffer (depth-1 overlap), A frags via
// ldmatrix.x4, B frags via paired ldmatrix.x4.trans. 2 CTAs/SM.
// grid = (6, 16, 12), block = 256. Output q/k/v as half.
// ---------------------------------------------------------------------------
#define ASTR 36               // u32 stride per 64-half A row
#define ABUF (128*ASTR)       // 4608 u32
#define BSTR 68               // u32 stride per 128-half B row (+pad)
#define BBUF (64*BSTR)        // 4352 u32
#define QSMEM_U32 (2*ABUF + 2*BBUF)   // 17920 u32 = 71680 B

__global__ __launch_bounds__(256, 2) void qkv_h_kernel(
    const __half* __restrict__ hsh, const __half* __restrict__ wh,
    const float* __restrict__ qb, const float* __restrict__ kb, const float* __restrict__ vb,
    __half* __restrict__ qp, __half* __restrict__ kp, __half* __restrict__ vp)
{
    extern __shared__ uint32_t smu[];
    uint32_t* As = smu;               // [2][ABUF]
    uint32_t* Bs = smu + 2 * ABUF;    // [2][BBUF]

    const int which = blockIdx.z >> 2, g = blockIdx.z & 3;
    const int m0 = blockIdx.y * 128, n0 = blockIdx.x * 128;
    const int tid = threadIdx.x, lane = tid & 31, wid = tid >> 5;
    const int wm = wid & 1, wn = wid >> 1;
    const int gq = lane >> 2, tg = lane & 3;

    const __half* Ag = hsh + (size_t)g * MPG * NC + (size_t)m0 * NC;
    const __half* Bg = wh + (size_t)(which * 4 + g) * NC * NC + n0;  // [k][n]
    const float*  bg = (which == 0 ? qb : which == 1 ? kb : vb) + (size_t)g * NC;
    __half*       op = (which == 0 ? qp : which == 1 ? kp : vp);

    float acc[4][4][4];
    #pragma unroll
    for (int i = 0; i < 4; i++)
        #pragma unroll
        for (int j = 0; j < 4; j++)
            #pragma unroll
            for (int q = 0; q < 4; q++) acc[i][j][q] = 0.f;

    const int alr = tid >> 1;          // A: 0..127 row
    const int alp = (tid & 1) * 32;    // A: half-offset within 64-half row
    const int blr = tid >> 2;          // B: 0..63 k-row
    const int blj = (tid & 3) * 4;     // B: uint4 group base

    // fragment lane mappings
    const int arow = (lane & 7) + ((lane >> 3) & 1) * 8;  // A ldmx4
    const int acol = ((lane >> 4) & 1) * 4;
    const int btrow = ((lane >> 3) & 1) * 8 + (lane & 7); // B ldmx4t row part
    const int btsel = ((lane >> 4) & 1) * 4;              // B ldmx4t col part

    // prologue: chunk 0 -> buf 0
    #pragma unroll
    for (int j = 0; j < 4; j++) {
        CP_ASYNC16(cvta_s(As + alr * ASTR + alp / 2 + j * 4),
                   Ag + (size_t)alr * NC + alp + j * 8);
        CP_ASYNC16(cvta_s(Bs + blr * BSTR + (blj + j) * 4),
                   Bg + (size_t)blr * NC + (blj + j) * 8);
    }
    CP_COMMIT();

    const int NCH = NC / 64;      // 12
    for (int c = 0; c < NCH; c++) {
        const int buf = c & 1;
        CP_WAIT0();
        __syncthreads();           // chunk c resident in buf

        if (c + 1 < NCH) {         // prefetch c+1 into other buf (overlaps compute)
            const int nb = buf ^ 1;
            const int kc = (c + 1) * 64;
            #pragma unroll
            for (int j = 0; j < 4; j++) {
                CP_ASYNC16(cvta_s(As + nb * ABUF + alr * ASTR + alp / 2 + j * 4),
                           Ag + (size_t)alr * NC + kc + alp + j * 8);
                CP_ASYNC16(cvta_s(Bs + nb * BBUF + blr * BSTR + (blj + j) * 4),
                           Bg + (size_t)(kc + blr) * NC + (blj + j) * 8);
            }
            CP_COMMIT();
        }

        // compute chunk c: 4 k16-steps x 4 mt x 4 nt mma
        {
            const uint32_t* Ab = As + buf * ABUF + (wm * 64) * ASTR;
            const uint32_t* Bb = Bs + buf * BBUF;
            #pragma unroll
            for (int kt = 0; kt < 4; kt++) {
                const int kk = kt * 8;
                uint32_t af[4][4], bf[4][2];
                #pragma unroll
                for (int mt = 0; mt < 4; mt++)
                    ldmx4(af[mt], cvta_s(Ab + (mt * 16 + arow) * ASTR + kk + acol));
                #pragma unroll
                for (int nt = 0; nt < 4; nt += 2) {
                    uint32_t t[4];
                    ldmx4t(t, cvta_s(Bb + (kt * 16 + btrow) * BSTR
                                     + wn * 16 + nt * 4 + btsel));
                    bf[nt][0] = t[0]; bf[nt][1] = t[1];
                    bf[nt + 1][0] = t[2]; bf[nt + 1][1] = t[3];
                }
                #pragma unroll
                for (int mt = 0; mt < 4; mt++)
                    #pragma unroll
                    for (int nt = 0; nt < 4; nt++)
                        mma_f16(acc[mt][nt], af[mt], bf[nt]);
            }
        }
        __syncthreads();           // all reads of buf done before reuse
    }

    // epilogue: bias add, pack to half, head-major scatter
    #pragma unroll
    for (int mt = 0; mt < 4; mt++) {
        const int row0 = m0 + wm * 64 + mt * 16 + gq;
        #pragma unroll
        for (int half_ = 0; half_ < 2; half_++) {
            const int trow = row0 + half_ * 8;
            const int b = trow >> 9, l = trow & 511;
            #pragma unroll
            for (int nt = 0; nt < 4; nt++) {
                const int col = n0 + wn * 32 + nt * 8 + 2 * tg;
                const int h = col >> 6, dh = col & 63;
                const float2 bv = *(const float2*)(bg + col);
                const uint32_t o = pkh(acc[mt][nt][half_ * 2 + 0] + bv.x,
                                       acc[mt][nt][half_ * 2 + 1] + bv.y);
                *(uint32_t*)(op + ((((size_t)g * NB + b) * NH + h) * LQ + l) * DH + dh) = o;
            }
        }
    }
}

// ---------------------------------------------------------------------------
// Online-softmax flash attention, fp16 mma.sync, 256 threads (8 warps).
// One CTA per (gbh, 128 queries). Warp w owns query rows [w*16, w*16+16).
// KV streamed in 8 chunks of 64 keys via cp.async 3-stage ring; 1 sync/chunk.
// K frags via paired ldmatrix.x4; V frags via paired ldmatrix.x4.trans.
// smem (u32): Q[128][36] | mask[512]f | 3 x (K[64][36] + V[64][36])
// ---------------------------------------------------------------------------
#define FQT  128
#define FSP  36                       // u32 stride per 64-half row
#define FO_Q   0
#define FO_MSK (FQT*FSP)              // 4608
#define FO_KV  (FO_MSK + 512)         // 5120
#define FKV_B  (2*64*FSP)             // 4608 u32 per ring buffer (K then V)
#define FASM_U32 (FO_KV + 3*FKV_B)    // 18944 u32 = 75776 B

__global__ __launch_bounds__(256, 2) void attn_flash_kernel(
    const __half* __restrict__ qg, const __half* __restrict__ kg,
    const __half* __restrict__ vg, const float* __restrict__ mask,
    float* __restrict__ out)
{
    extern __shared__ uint32_t smu[];
    uint32_t* Qs  = smu + FO_Q;
    float*    Msk = (float*)(smu + FO_MSK);
    uint32_t* KVr = smu + FO_KV;

    const int gbh = blockIdx.y;
    const int l0q = blockIdx.x * FQT;
    const int h   = gbh % NH;
    const int gb  = gbh / NH;
    const int tid  = threadIdx.x;
    const int lane = tid & 31;
    const int wid  = tid >> 5;          // 0..7
    const int gq = lane >> 2, tg = lane & 3;

    const __half* Q  = qg + (size_t)gbh * LQ * DH + (size_t)l0q * DH;
    const __half* K  = kg + (size_t)gbh * LQ * DH;
    const __half* V  = vg + (size_t)gbh * LQ * DH;
    const float*  mk = mask + (size_t)gb * LQ;

    // ---- stage Q tile + mask ----
    #pragma unroll
    for (int i = 0; i < 4; i++) {
        const int idx = i * 256 + tid;
        const int r = idx >> 3, j = idx & 7;
        *(uint4*)(Qs + r * FSP + j * 4) =
            *(const uint4*)(Q + (size_t)r * DH + j * 8);
    }
    Msk[tid] = mk[tid];
    Msk[tid + 256] = mk[tid + 256];

    // ---- cp.async prologue: chunks 0,1 -> buffers 0,1 ----
    const int clr = tid >> 2;
    const int clj = (tid & 3) * 2;
    #pragma unroll
    for (int pc = 0; pc < 2; pc++) {
        uint32_t* B = KVr + pc * FKV_B;
        #pragma unroll
        for (int j = 0; j < 2; j++) {
            CP_ASYNC16(cvta_s(B + clr * FSP + (clj + j) * 4),
                       K + (size_t)(pc * 64 + clr) * DH + (clj + j) * 8);
            CP_ASYNC16(cvta_s(B + 64 * FSP + clr * FSP + (clj + j) * 4),
                       V + (size_t)(pc * 64 + clr) * DH + (clj + j) * 8);
        }
        CP_COMMIT();
    }

    uint32_t qf[4][4];
    float ctx[8][4];
    #pragma unroll
    for (int ntd = 0; ntd < 8; ntd++)
        #pragma unroll
        for (int q = 0; q < 4; q++) ctx[ntd][q] = 0.f;
    float m0 = -1e30f, m1 = -1e30f, sl0 = 0.f, sl1 = 0.f;

    const float scale = 0.125f;
    const int qrow = (lane & 7) + ((lane >> 3) & 1) * 8;
    const int qcol = ((lane >> 4) & 1) * 4;
    // K paired x4 (non-trans): rows (nt + lane>>4)*8 + (lane&7), col +((lane>>3)&1)*4
    const int k4row = (lane >> 4) * 8 + (lane & 7);
    const int k4col = ((lane >> 3) & 1) * 4;
    // V paired x4.trans: rows ((lane>>3)&1)*8 + (lane&7), col +((lane>>4)&1)*4
    const int v4row = ((lane >> 3) & 1) * 8 + (lane & 7);
    const int v4col = ((lane >> 4) & 1) * 4;
    bool qf_loaded = false;

    for (int c = 0; c < 8; c++) {
        if (c < 7) { CP_WAIT1(); } else { CP_WAIT0(); }
        __syncthreads();                    // chunk c resident in buf c%3

        if (c + 2 < 8) {
            uint32_t* B = KVr + ((c + 2) % 3) * FKV_B;
            #pragma unroll
            for (int j = 0; j < 2; j++) {
                CP_ASYNC16(cvta_s(B + clr * FSP + (clj + j) * 4),
                           K + (size_t)((c + 2) * 64 + clr) * DH + (clj + j) * 8);
                CP_ASYNC16(cvta_s(B + 64 * FSP + clr * FSP + (clj + j) * 4),
                           V + (size_t)((c + 2) * 64 + clr) * DH + (clj + j) * 8);
            }
            CP_COMMIT();
        }

        if (!qf_loaded) {
            #pragma unroll
            for (int ks = 0; ks < 4; ks++)
                ldmx4(qf[ks], cvta_s(Qs + (wid * 16 + qrow) * FSP + ks * 8 + qcol));
            qf_loaded = true;
        }

        const uint32_t* Kb = KVr + (c % 3) * FKV_B;
        const uint32_t* Vb = Kb + 64 * FSP;

        // ---- QK^T: 16 queries x 64 keys; K frags via paired ldmx4 ----
        float s[8][4];
        #pragma unroll
        for (int nt = 0; nt < 8; nt++)
            #pragma unroll
            for (int q = 0; q < 4; q++) s[nt][q] = 0.f;
        #pragma unroll
        for (int ks = 0; ks < 4; ks++)
            #pragma unroll
            for (int nt = 0; nt < 8; nt += 2) {
                uint32_t t[4];
                ldmx4(t, cvta_s(Kb + (nt * 8 + k4row) * FSP + ks * 8 + k4col));
                mma_f16(s[nt],     qf[ks], t);
                mma_f16(s[nt + 1], qf[ks], t + 2);
            }

        // ---- scale + mask + chunk row max ----
        float cm0 = -1e30f, cm1 = -1e30f;
        #pragma unroll
        for (int nt = 0; nt < 8; nt++) {
            const int col = c * 64 + nt * 8 + 2 * tg;
            const float mv0 = Msk[col], mv1 = Msk[col + 1];
            s[nt][0] = fmaf(s[nt][0], scale, mv0);
            s[nt][1] = fmaf(s[nt][1], scale, mv1);
            s[nt][2] = fmaf(s[nt][2], scale, mv0);
            s[nt][3] = fmaf(s[nt][3], scale, mv1);
            cm0 = fmaxf(cm0, fmaxf(s[nt][0], s[nt][1]));
            cm1 = fmaxf(cm1, fmaxf(s[nt][2], s[nt][3]));
        }
        cm0 = fmaxf(cm0, __shfl_xor_sync(0xFFFFFFFFu, cm0, 1));
        cm0 = fmaxf(cm0, __shfl_xor_sync(0xFFFFFFFFu, cm0, 2));
        cm1 = fmaxf(cm1, __shfl_xor_sync(0xFFFFFFFFu, cm1, 1));
        cm1 = fmaxf(cm1, __shfl_xor_sync(0xFFFFFFFFu, cm1, 2));

        // ---- online rescale ----
        const float nm0 = fmaxf(m0, cm0), nm1 = fmaxf(m1, cm1);
        const float f0 = fast_exp(m0 - nm0), f1 = fast_exp(m1 - nm1);
        m0 = nm0; m1 = nm1;

        // ---- exp -> packed half2 A-frags, chunk sums ----
        uint32_t ph[8][2];
        float cs0 = 0.f, cs1 = 0.f;
        #pragma unroll
        for (int nt = 0; nt < 8; nt++) {
            const float e0 = fast_exp(s[nt][0] - nm0);
            const float e1 = fast_exp(s[nt][1] - nm0);
            const float e2 = fast_exp(s[nt][2] - nm1);
            const float e3 = fast_exp(s[nt][3] - nm1);
            cs0 += e0 + e1;
            cs1 += e2 + e3;
            ph[nt][0] = pkh(e0, e1);
            ph[nt][1] = pkh(e2, e3);
        }
        cs0 += __shfl_xor_sync(0xFFFFFFFFu, cs0, 1);
        cs0 += __shfl_xor_sync(0xFFFFFFFFu, cs0, 2);
        cs1 += __shfl_xor_sync(0xFFFFFFFFu, cs1, 1);
        cs1 += __shfl_xor_sync(0xFFFFFFFFu, cs1, 2);
        sl0 = sl0 * f0 + cs0;
        sl1 = sl1 * f1 + cs1;

        #pragma unroll
        for (int ntd = 0; ntd < 8; ntd++) {
            ctx[ntd][0] *= f0; ctx[ntd][1] *= f0;
            ctx[ntd][2] *= f1; ctx[ntd][3] *= f1;
        }

        // ---- PV: P(16x64) @ V(64x64); V frags via paired ldmx4t ----
        #pragma unroll
        for (int kt = 0; kt < 4; kt++) {
            uint32_t av[4];
            av[0] = ph[2 * kt][0];
            av[1] = ph[2 * kt][1];
            av[2] = ph[2 * kt + 1][0];
            av[3] = ph[2 * kt + 1][1];
            const uint32_t* vp0 = Vb + (kt * 16 + v4row) * FSP;
            #pragma unroll
            for (int ntd = 0; ntd < 8; ntd += 2) {
                uint32_t t[4];
                ldmx4t(t, cvta_s(vp0 + ntd * 4 + v4col));
                mma_f16(ctx[ntd],     av, t);
                mma_f16(ctx[ntd + 1], av, t + 2);
            }
        }
    }

    // ---- epilogue: normalize, write out ----
    const float iv0 = 1.0f / sl0, iv1 = 1.0f / sl1;
    const size_t row0 = (size_t)gb * LQ + l0q + wid * 16 + gq;
    const int colo = h * DH + 2 * tg;
    #pragma unroll
    for (int ntd = 0; ntd < 8; ntd++) {
        *(float2*)(out + row0 * NC + colo + ntd * 8) =
            make_float2(ctx[ntd][0] * iv0, ctx[ntd][1] * iv0);
        *(float2*)(out + (row0 + 8) * NC + colo + ntd * 8) =
            make_float2(ctx[ntd][2] * iv1, ctx[ntd][3] * iv1);
    }
}

// ---------------------------------------------------------------------------
extern "C" void kernel_launch(void* const* d_in, const int* in_sizes, int n_in,
                              void* d_out, int out_size)
{
    (void)in_sizes; (void)n_in; (void)out_size;
    const float* hs   = (const float*)d_in[0];
    const float* mask = (const float*)d_in[1];
    const float* qw   = (const float*)d_in[2];
    const float* qb   = (const float*)d_in[3];
    const float* kw   = (const float*)d_in[4];
    const float* kb   = (const float*)d_in[5];
    const float* vw   = (const float*)d_in[6];
    const float* vb   = (const float*)d_in[7];
    float* out = (float*)d_out;

    void *qp, *kp, *vp, *wp, *hsp;
    cudaGetSymbolAddress(&qp, g_qh);
    cudaGetSymbolAddress(&kp, g_kh);
    cudaGetSymbolAddress(&vp, g_vh);
    cudaGetSymbolAddress(&wp, g_wh);
    cudaGetSymbolAddress(&hsp, g_hsh);

    hs_convert_kernel<<<NG * MPG * NC / 1024, 256>>>(hs, (__half*)hsp);

    dim3 wgrid(NC * NC / 1024, 12);
    w_convert_kernel<<<wgrid, 256>>>(qw, kw, vw, (__half*)wp);

    const int gsmem = QSMEM_U32 * (int)sizeof(uint32_t);  // 71680
    cudaFuncSetAttribute(qkv_h_kernel,
                         cudaFuncAttributeMaxDynamicSharedMemorySize, gsmem);
    dim3 ggrid(NC / 128, MPG / 128, 12);
    qkv_h_kernel<<<ggrid, 256, gsmem>>>((const __half*)hsp, (const __half*)wp,
                                        qb, kb, vb,
                                        (__half*)qp, (__half*)kp, (__half*)vp);

    const int asmem = FASM_U32 * (int)sizeof(uint32_t);   // 75776
    cudaFuncSetAttribute(attn_flash_kernel,
                         cudaFuncAttributeMaxDynamicSharedMemorySize, asmem);
    dim3 agrid(LQ / FQT, NG * NB * NH);
    attn_flash_kernel<<<agrid, 256, asmem>>>((const __half*)qp, (const __half*)kp,
                                             (const __half*)vp, mask, out);
}